// round 11
// baseline (speedup 1.0000x reference)
#include <cuda_runtime.h>
#include <cuda_bf16.h>
#include <math.h>
#include <stdint.h>

// Problem constants (fixed by the dataset)
#define NN    50000     // nodes
#define EE    800000    // edges
#define C_IN  128
#define C_HID 256
#define C_OUT 64

// ---------------- scratch (device globals; no allocation, no host API) -----
__device__ int   g_is64;            // 1 if edge_index delivered as int64
__device__ int   g_row[EE];
__device__ int   g_col[EE];
__device__ int   g_deg[NN];
__device__ float g_dinv[NN];
__device__ int   g_off[NN + 1];
__device__ int   g_cursor[NN];
__device__ int   g_csr[EE];
__device__ unsigned long long g_pkt[64];   // lookback packets: value<<2 | flag
__device__ float g_bufA[(size_t)NN * C_HID];
__device__ float g_bufB[(size_t)NN * C_HID];

// ---------------- prep ------------------------------------------------------
// zero degrees + lookback packets + (thread 0) sniff edge_index dtype:
// int64 node ids < 2^31 have every odd int32 word == 0.
__global__ void k_zero_deg(const int* __restrict__ ei32, int n) {
    int i = blockIdx.x * blockDim.x + threadIdx.x;
    if (i < n) g_deg[i] = 0;
    if (i < 64) g_pkt[i] = 0ULL;
    if (blockIdx.x == 0 && threadIdx.x == 0) {
        int all_zero = 1;
        #pragma unroll
        for (int k = 0; k < 64; k++)
            if (ei32[2 * k + 1] != 0) all_zero = 0;
        g_is64 = all_zero;
    }
}

__global__ void k_prep_edges(const void* __restrict__ ei, int e) {
    int idx = blockIdx.x * blockDim.x + threadIdx.x;
    if (idx >= e) return;
    int r, c;
    if (g_is64) {
        const long long* p = (const long long*)ei;
        r = (int)p[idx];
        c = (int)p[(size_t)e + idx];
    } else {
        const int* p = (const int*)ei;
        r = p[idx];
        c = p[(size_t)e + idx];
    }
    g_row[idx] = r;
    g_col[idx] = c;
    atomicAdd(&g_deg[c], 1);
}

// single-pass decoupled-lookback scan: g_deg -> g_off/g_cursor, dinv fused.
// 49 blocks of 1024, all resident (<=148 SMs) -> lookback can't deadlock.
__global__ void k_scan(int n) {
    __shared__ int wsum[32];
    __shared__ int s_excl;
    const int b = blockIdx.x;
    const int i = b * 1024 + threadIdx.x;
    const int v = (i < n) ? g_deg[i] : 0;
    const int lane = threadIdx.x & 31, w = threadIdx.x >> 5;

    int s = v;
    #pragma unroll
    for (int d = 1; d < 32; d <<= 1) {
        int t = __shfl_up_sync(~0u, s, d);
        if (lane >= d) s += t;
    }
    if (lane == 31) wsum[w] = s;
    __syncthreads();
    if (w == 0) {
        int ws = wsum[lane];
        #pragma unroll
        for (int d = 1; d < 32; d <<= 1) {
            int t = __shfl_up_sync(~0u, ws, d);
            if (lane >= d) ws += t;
        }
        wsum[lane] = ws;
    }
    __syncthreads();
    const int excl = s - v + (w > 0 ? wsum[w - 1] : 0);
    const int btotal = wsum[31];

    if (threadIdx.x == 0) {
        int ex = 0;
        if (b == 0) {
            atomicExch(&g_pkt[0], ((unsigned long long)btotal << 2) | 2ULL);
        } else {
            atomicExch(&g_pkt[b], ((unsigned long long)btotal << 2) | 1ULL);
            for (int j = b - 1; j >= 0;) {
                unsigned long long p;
                do { p = atomicAdd(&g_pkt[j], 0ULL); } while ((p & 3ULL) == 0ULL);
                ex += (int)(p >> 2);
                if ((p & 3ULL) == 2ULL) break;
                j--;
            }
            atomicExch(&g_pkt[b], ((unsigned long long)(ex + btotal) << 2) | 2ULL);
        }
        s_excl = ex;
    }
    __syncthreads();

    const int off = s_excl + excl;
    if (i < n) {
        g_off[i] = off;
        g_cursor[i] = off;
        g_dinv[i] = rsqrtf((float)(v + 1));
    }
    if (i == n - 1) g_off[n] = off + v;
}

__global__ void k_fill_csr(int e) {
    int idx = blockIdx.x * blockDim.x + threadIdx.x;
    if (idx >= e) return;
    int c = g_col[idx];
    int p = atomicAdd(&g_cursor[c], 1);
    g_csr[p] = g_row[idx];
}

// ---------------- tf32 helpers ----------------------------------------------
__device__ __forceinline__ uint32_t f2tf(float f) {
    uint32_t u;
    asm("cvt.rna.tf32.f32 %0, %1;" : "=r"(u) : "f"(f));
    return u;
}

__device__ __forceinline__ void mma_tf32(float c[4], const uint32_t a[4],
                                         const uint32_t b[2]) {
    asm volatile(
        "mma.sync.aligned.m16n8k8.row.col.f32.tf32.tf32.f32 "
        "{%0,%1,%2,%3}, {%4,%5,%6,%7}, {%8,%9}, {%0,%1,%2,%3};"
        : "+f"(c[0]), "+f"(c[1]), "+f"(c[2]), "+f"(c[3])
        : "r"(a[0]), "r"(a[1]), "r"(a[2]), "r"(a[3]), "r"(b[0]), "r"(b[1]));
}

// ---------------- tf32 GEMM: Out[N,M] = A[N,K] @ W[K,M] (+bias, +sigmoid) ----
// BM=128, BK=16, double-buffered smem, 256 threads (8 warps as 4x2),
// warp tile 32 x (BN/2). Conflict-free smem strides: As 20, Bs BN+8.
template <int BN, bool SRC_B, bool DST_A, bool SIG, bool BIAS>
__global__ __launch_bounds__(256, 2)
void k_gemm_tf32(const float* __restrict__ W, const float* __restrict__ bias,
                 int N, int K, int M) {
    const float* __restrict__ A = SRC_B ? (const float*)g_bufB : (const float*)g_bufA;
    float* __restrict__ Out = DST_A ? (float*)g_bufA : (float*)g_bufB;

    constexpr int WN   = BN / 2;               // warp tile N
    constexpr int NT   = WN / 8;               // m16n8 tiles per warp
    constexpr int NBLD = (BN == 128) ? 2 : 1;  // B float4 loads per thread/stage

    __shared__ __align__(16) float As[2][128][20];     // stride 20: banks gi*4+ci unique
    __shared__ __align__(16) float Bs[2][16][BN + 8];  // stride mod 32 = 8: ci*8+gi unique

    const int tid  = threadIdx.x;
    const int lane = tid & 31;
    const int warp = tid >> 5;
    const int wm   = warp >> 1;           // 0..3
    const int wn   = warp & 1;            // 0..1
    const int gi   = lane >> 2;           // 0..7
    const int ci   = lane & 3;            // 0..3
    const int row0 = blockIdx.y * 128;
    const int col0 = blockIdx.x * BN;

    float c[2][NT][4];
    #pragma unroll
    for (int mt = 0; mt < 2; mt++)
        #pragma unroll
        for (int nt = 0; nt < NT; nt++)
            #pragma unroll
            for (int j = 0; j < 4; j++) c[mt][nt][j] = 0.f;

    uint32_t aT[2][4];
    uint32_t bT[NBLD][4];
    const int KB = K / 16;

    auto load_regs = [&](int kb) {
        #pragma unroll
        for (int i = 0; i < 2; i++) {
            int idx = tid + i * 256;
            int r   = idx >> 2;            // 4 float4 chunks per 16-wide row
            int kc  = (idx & 3) * 4;
            float4 v = make_float4(0.f, 0.f, 0.f, 0.f);
            if (row0 + r < N)
                v = *(const float4*)(A + (size_t)(row0 + r) * K + kb * 16 + kc);
            aT[i][0] = f2tf(v.x); aT[i][1] = f2tf(v.y);
            aT[i][2] = f2tf(v.z); aT[i][3] = f2tf(v.w);
        }
        #pragma unroll
        for (int i = 0; i < NBLD; i++) {
            int idx = tid + i * 256;
            int r, nc;
            if (BN == 128) { r = idx >> 5; nc = (idx & 31) * 4; }
            else           { r = idx >> 4; nc = (idx & 15) * 4; }
            float4 v = *(const float4*)(W + (size_t)(kb * 16 + r) * M + col0 + nc);
            bT[i][0] = f2tf(v.x); bT[i][1] = f2tf(v.y);
            bT[i][2] = f2tf(v.z); bT[i][3] = f2tf(v.w);
        }
    };
    auto store_regs = [&](int s) {
        #pragma unroll
        for (int i = 0; i < 2; i++) {
            int idx = tid + i * 256;
            int r   = idx >> 2;
            int kc  = (idx & 3) * 4;
            *(uint4*)&As[s][r][kc] = *(uint4*)aT[i];
        }
        #pragma unroll
        for (int i = 0; i < NBLD; i++) {
            int idx = tid + i * 256;
            int r, nc;
            if (BN == 128) { r = idx >> 5; nc = (idx & 31) * 4; }
            else           { r = idx >> 4; nc = (idx & 15) * 4; }
            *(uint4*)&Bs[s][r][nc] = *(uint4*)bT[i];
        }
    };

    load_regs(0);
    store_regs(0);
    __syncthreads();

    for (int kb = 0; kb < KB; kb++) {
        if (kb + 1 < KB) load_regs(kb + 1);   // LDG in flight over the mma burst
        const int s = kb & 1;

        #pragma unroll
        for (int kk = 0; kk < 2; kk++) {
            const int k8 = kk * 8;
            uint32_t a[2][4];
            #pragma unroll
            for (int mt = 0; mt < 2; mt++) {
                int mr = wm * 32 + mt * 16 + gi;
                a[mt][0] = __float_as_uint(As[s][mr    ][k8     + ci]);
                a[mt][1] = __float_as_uint(As[s][mr + 8][k8     + ci]);
                a[mt][2] = __float_as_uint(As[s][mr    ][k8 + 4 + ci]);
                a[mt][3] = __float_as_uint(As[s][mr + 8][k8 + 4 + ci]);
            }
            uint32_t b[NT][2];
            #pragma unroll
            for (int nt = 0; nt < NT; nt++) {
                int nc = wn * WN + nt * 8 + gi;
                b[nt][0] = __float_as_uint(Bs[s][k8     + ci][nc]);
                b[nt][1] = __float_as_uint(Bs[s][k8 + 4 + ci][nc]);
            }
            #pragma unroll
            for (int mt = 0; mt < 2; mt++)
                #pragma unroll
                for (int nt = 0; nt < NT; nt++)
                    mma_tf32(c[mt][nt], a[mt], b[nt]);
        }

        if (kb + 1 < KB) {
            store_regs((kb + 1) & 1);   // other buffer; prior sync guarantees readers done
            __syncthreads();
        }
    }

    // ---- epilogue: (+bias), (sigmoid), store float2 pairs
    #pragma unroll
    for (int mt = 0; mt < 2; mt++) {
        int r = row0 + wm * 32 + mt * 16 + gi;
        #pragma unroll
        for (int nt = 0; nt < NT; nt++) {
            int gcol = col0 + wn * WN + nt * 8 + ci * 2;
            float b0 = 0.f, b1 = 0.f;
            if (BIAS) { b0 = __ldg(bias + gcol); b1 = __ldg(bias + gcol + 1); }
            float v0 = c[mt][nt][0] + b0, v1 = c[mt][nt][1] + b1;
            float v2 = c[mt][nt][2] + b0, v3 = c[mt][nt][3] + b1;
            if (SIG) {
                v0 = 1.f / (1.f + __expf(-v0));
                v1 = 1.f / (1.f + __expf(-v1));
                v2 = 1.f / (1.f + __expf(-v2));
                v3 = 1.f / (1.f + __expf(-v3));
            }
            if (r < N)
                *(float2*)(Out + (size_t)r * M + gcol) = make_float2(v0, v1);
            if (r + 8 < N)
                *(float2*)(Out + (size_t)(r + 8) * M + gcol) = make_float2(v2, v3);
        }
    }
}

// ---------------- aggregation (float4 lanes, 4-edge ILP) ---------------------
// out[i] = dinv[i] * ( sum_r dinv[r]*in[r] + dinv[i]*in[i] )  (+bias)
// SRCSEL: 0=g_bufA, 1=g_bufB, 2=external
template <int C, int SRCSEL, bool OUT_EXT, bool BIAS>
__global__ __launch_bounds__(128)
void k_agg(const float* __restrict__ in_ext, const float* __restrict__ bias,
           float* __restrict__ out_ext) {
    constexpr int T   = C / 4;       // threads per node
    constexpr int NPB = 128 / T;     // nodes per block
    const float* __restrict__ in =
        (SRCSEL == 2) ? in_ext
        : (SRCSEL == 0 ? (const float*)g_bufA : (const float*)g_bufB);
    float* __restrict__ out = OUT_EXT ? out_ext : (float*)g_bufA;

    const int node = blockIdx.x * NPB + threadIdx.x / T;
    if (node >= NN) return;
    const int c4 = (threadIdx.x % T) * 4;

    const float di = g_dinv[node];
    float4 s = __ldg((const float4*)(in + (size_t)node * C + c4));
    float ax = di * s.x, ay = di * s.y, az = di * s.z, aw = di * s.w;

    int p = g_off[node];
    const int e = g_off[node + 1];
    for (; p + 3 < e; p += 4) {
        int r0 = g_csr[p],     r1 = g_csr[p + 1];
        int r2 = g_csr[p + 2], r3 = g_csr[p + 3];
        float d0 = g_dinv[r0], d1 = g_dinv[r1];
        float d2 = g_dinv[r2], d3 = g_dinv[r3];
        float4 v0 = __ldg((const float4*)(in + (size_t)r0 * C + c4));
        float4 v1 = __ldg((const float4*)(in + (size_t)r1 * C + c4));
        float4 v2 = __ldg((const float4*)(in + (size_t)r2 * C + c4));
        float4 v3 = __ldg((const float4*)(in + (size_t)r3 * C + c4));
        ax += d0 * v0.x + d1 * v1.x + d2 * v2.x + d3 * v3.x;
        ay += d0 * v0.y + d1 * v1.y + d2 * v2.y + d3 * v3.y;
        az += d0 * v0.z + d1 * v1.z + d2 * v2.z + d3 * v3.z;
        aw += d0 * v0.w + d1 * v1.w + d2 * v2.w + d3 * v3.w;
    }
    for (; p < e; p++) {
        int r = g_csr[p];
        float d = g_dinv[r];
        float4 v = __ldg((const float4*)(in + (size_t)r * C + c4));
        ax += d * v.x; ay += d * v.y; az += d * v.z; aw += d * v.w;
    }

    float4 o = make_float4(di * ax, di * ay, di * az, di * aw);
    if (BIAS) {
        float4 b = __ldg((const float4*)(bias + c4));
        o.x += b.x; o.y += b.y; o.z += b.z; o.w += b.w;
    }
    *(float4*)(out + (size_t)node * C + c4) = o;
}

// ---------------- launch: kernel launches ONLY -------------------------------
extern "C" void kernel_launch(void* const* d_in, const int* in_sizes, int n_in,
                              void* d_out, int out_size) {
    const float* x   = (const float*)d_in[0];
    // d_in[1] = edge_attr (unused by forward)
    const void*  ei  = d_in[2];
    const float* W1  = (const float*)d_in[3];
    const float* b1  = (const float*)d_in[4];
    const float* W2  = (const float*)d_in[5];
    const float* b2  = (const float*)d_in[6];
    const float* W3  = (const float*)d_in[7];
    const float* b3  = (const float*)d_in[8];
    float*       out = (float*)d_out;

    const int n = NN;
    const int e = in_sizes[2] / 2;             // 800000
    const int nblk = (n + 1023) / 1024;        // 49

    // ---- graph preprocessing
    k_zero_deg<<<(n + 255) / 256, 256>>>((const int*)ei, n);
    k_prep_edges<<<(e + 255) / 256, 256>>>(ei, e);
    k_scan<<<nblk, 1024>>>(n);
    k_fill_csr<<<(e + 255) / 256, 256>>>(e);

    // ---- layer 1: aggregate x (128ch) -> bufA; GEMM+bias+sigmoid -> bufB
    k_agg<C_IN, 2, false, false><<<NN / 4, 128>>>(x, nullptr, nullptr);
    {
        dim3 grid(C_HID / 128, (n + 127) / 128);
        k_gemm_tf32<128, false, false, true, true><<<grid, 256>>>(W1, b1, n, C_IN, C_HID);
    }
    // ---- layer 2: aggregate bufB (256ch) -> bufA; GEMM+bias+sigmoid -> bufB
    k_agg<C_HID, 1, false, false><<<NN / 2, 128>>>(nullptr, nullptr, nullptr);
    {
        dim3 grid(C_HID / 128, (n + 127) / 128);
        k_gemm_tf32<128, false, false, true, true><<<grid, 256>>>(W2, b2, n, C_HID, C_HID);
    }
    // ---- layer 3: GEMM bufB @ W3 -> bufA (64ch); aggregate + bias -> out
    {
        dim3 grid(C_OUT / 64, (n + 127) / 128);
        k_gemm_tf32<64, true, true, false, false><<<grid, 256>>>(W3, nullptr, n, C_HID, C_OUT);
    }
    k_agg<C_OUT, 0, true, true><<<NN / 8, 128>>>(nullptr, b3, out);
}

// round 12
// speedup vs baseline: 1.0582x; 1.0582x over previous
#include <cuda_runtime.h>
#include <cuda_bf16.h>
#include <math.h>
#include <stdint.h>

// Problem constants (fixed by the dataset)
#define NN    50000     // nodes
#define EE    800000    // edges
#define C_IN  128
#define C_HID 256
#define C_OUT 64

// ---------------- scratch (device globals; no allocation, no host API) -----
__device__ int   g_is64;            // 1 if edge_index delivered as int64
__device__ int   g_deg[NN];
__device__ float g_dinv[NN];
__device__ int   g_off[NN + 1];
__device__ int   g_cursor[NN];
__device__ int   g_csr[EE];
__device__ unsigned long long g_pkt[64];   // lookback packets: value<<2 | flag
__device__ float g_bufA[(size_t)NN * C_HID];
__device__ float g_bufB[(size_t)NN * C_HID];

// ---------------- prep ------------------------------------------------------
// zero degrees + lookback packets + (thread 0) sniff edge_index dtype:
// int64 node ids < 2^31 have every odd int32 word == 0.
__global__ void k_zero_deg(const int* __restrict__ ei32, int n) {
    int i = blockIdx.x * blockDim.x + threadIdx.x;
    if (i < n) g_deg[i] = 0;
    if (i < 64) g_pkt[i] = 0ULL;
    if (blockIdx.x == 0 && threadIdx.x == 0) {
        int all_zero = 1;
        #pragma unroll
        for (int k = 0; k < 64; k++)
            if (ei32[2 * k + 1] != 0) all_zero = 0;
        g_is64 = all_zero;
    }
}

// degree count only (reads just the col half of edge_index)
__global__ void k_prep_edges(const void* __restrict__ ei, int e) {
    int idx = blockIdx.x * blockDim.x + threadIdx.x;
    if (idx >= e) return;
    int c;
    if (g_is64) c = (int)((const long long*)ei)[(size_t)e + idx];
    else        c = ((const int*)ei)[(size_t)e + idx];
    atomicAdd(&g_deg[c], 1);
}

// single-pass decoupled-lookback scan: g_deg -> g_off/g_cursor, dinv fused.
// 49 blocks of 1024, all resident (<=148 SMs) -> lookback can't deadlock.
__global__ void k_scan(int n) {
    __shared__ int wsum[32];
    __shared__ int s_excl;
    const int b = blockIdx.x;
    const int i = b * 1024 + threadIdx.x;
    const int v = (i < n) ? g_deg[i] : 0;
    const int lane = threadIdx.x & 31, w = threadIdx.x >> 5;

    int s = v;
    #pragma unroll
    for (int d = 1; d < 32; d <<= 1) {
        int t = __shfl_up_sync(~0u, s, d);
        if (lane >= d) s += t;
    }
    if (lane == 31) wsum[w] = s;
    __syncthreads();
    if (w == 0) {
        int ws = wsum[lane];
        #pragma unroll
        for (int d = 1; d < 32; d <<= 1) {
            int t = __shfl_up_sync(~0u, ws, d);
            if (lane >= d) ws += t;
        }
        wsum[lane] = ws;
    }
    __syncthreads();
    const int excl = s - v + (w > 0 ? wsum[w - 1] : 0);
    const int btotal = wsum[31];

    if (threadIdx.x == 0) {
        int ex = 0;
        if (b == 0) {
            atomicExch(&g_pkt[0], ((unsigned long long)btotal << 2) | 2ULL);
        } else {
            atomicExch(&g_pkt[b], ((unsigned long long)btotal << 2) | 1ULL);
            for (int j = b - 1; j >= 0;) {
                unsigned long long p;
                do { p = atomicAdd(&g_pkt[j], 0ULL); } while ((p & 3ULL) == 0ULL);
                ex += (int)(p >> 2);
                if ((p & 3ULL) == 2ULL) break;
                j--;
            }
            atomicExch(&g_pkt[b], ((unsigned long long)(ex + btotal) << 2) | 2ULL);
        }
        s_excl = ex;
    }
    __syncthreads();

    const int off = s_excl + excl;
    if (i < n) {
        g_off[i] = off;
        g_cursor[i] = off;
        g_dinv[i] = rsqrtf((float)(v + 1));
    }
    if (i == n - 1) g_off[n] = off + v;
}

// fill CSR reading edge_index directly (no row/col staging arrays)
__global__ void k_fill_csr(const void* __restrict__ ei, int e) {
    int idx = blockIdx.x * blockDim.x + threadIdx.x;
    if (idx >= e) return;
    int r, c;
    if (g_is64) {
        const long long* p = (const long long*)ei;
        r = (int)p[idx];
        c = (int)p[(size_t)e + idx];
    } else {
        const int* p = (const int*)ei;
        r = p[idx];
        c = p[(size_t)e + idx];
    }
    int pos = atomicAdd(&g_cursor[c], 1);
    g_csr[pos] = r;
}

// ---------------- tf32 helpers ----------------------------------------------
__device__ __forceinline__ uint32_t f2tf(float f) {
    uint32_t u;
    asm("cvt.rna.tf32.f32 %0, %1;" : "=r"(u) : "f"(f));
    return u;
}

__device__ __forceinline__ void mma_tf32(float c[4], const uint32_t a[4],
                                         const uint32_t b[2]) {
    asm volatile(
        "mma.sync.aligned.m16n8k8.row.col.f32.tf32.tf32.f32 "
        "{%0,%1,%2,%3}, {%4,%5,%6,%7}, {%8,%9}, {%0,%1,%2,%3};"
        : "+f"(c[0]), "+f"(c[1]), "+f"(c[2]), "+f"(c[3])
        : "r"(a[0]), "r"(a[1]), "r"(a[2]), "r"(a[3]), "r"(b[0]), "r"(b[1]));
}

// ---------------- tf32 GEMM: Out[N,M] = A[N,K] @ W[K,M] ----------------------
// (+bias, +sigmoid, optional row pre-scale by dinv for downstream aggregation)
// BM=128, BK=16, double-buffered smem, 256 threads (8 warps as 4x2),
// warp tile 32 x (BN/2). Conflict-free smem strides: As 20, Bs BN+8.
template <int BN, bool SRC_B, bool DST_A, bool SIG, bool BIAS, bool DSC>
__global__ __launch_bounds__(256)
void k_gemm_tf32(const float* __restrict__ W, const float* __restrict__ bias,
                 int N, int K, int M) {
    const float* __restrict__ A = SRC_B ? (const float*)g_bufB : (const float*)g_bufA;
    float* __restrict__ Out = DST_A ? (float*)g_bufA : (float*)g_bufB;

    constexpr int WN   = BN / 2;               // warp tile N
    constexpr int NT   = WN / 8;               // m16n8 tiles per warp
    constexpr int NBLD = (BN == 128) ? 2 : 1;  // B float4 loads per thread/stage

    __shared__ __align__(16) float As[2][128][20];     // stride 20: banks gi*4+ci unique
    __shared__ __align__(16) float Bs[2][16][BN + 8];  // stride mod 32 = 8: ci*8+gi unique

    const int tid  = threadIdx.x;
    const int lane = tid & 31;
    const int warp = tid >> 5;
    const int wm   = warp >> 1;           // 0..3
    const int wn   = warp & 1;            // 0..1
    const int gi   = lane >> 2;           // 0..7
    const int ci   = lane & 3;            // 0..3
    const int row0 = blockIdx.y * 128;
    const int col0 = blockIdx.x * BN;

    float c[2][NT][4];
    #pragma unroll
    for (int mt = 0; mt < 2; mt++)
        #pragma unroll
        for (int nt = 0; nt < NT; nt++)
            #pragma unroll
            for (int j = 0; j < 4; j++) c[mt][nt][j] = 0.f;

    uint32_t aT[2][4];
    uint32_t bT[NBLD][4];
    const int KB = K / 16;

    auto load_regs = [&](int kb) {
        #pragma unroll
        for (int i = 0; i < 2; i++) {
            int idx = tid + i * 256;
            int r   = idx >> 2;            // 4 float4 chunks per 16-wide row
            int kc  = (idx & 3) * 4;
            float4 v = make_float4(0.f, 0.f, 0.f, 0.f);
            if (row0 + r < N)
                v = *(const float4*)(A + (size_t)(row0 + r) * K + kb * 16 + kc);
            aT[i][0] = f2tf(v.x); aT[i][1] = f2tf(v.y);
            aT[i][2] = f2tf(v.z); aT[i][3] = f2tf(v.w);
        }
        #pragma unroll
        for (int i = 0; i < NBLD; i++) {
            int idx = tid + i * 256;
            int r, nc;
            if (BN == 128) { r = idx >> 5; nc = (idx & 31) * 4; }
            else           { r = idx >> 4; nc = (idx & 15) * 4; }
            float4 v = *(const float4*)(W + (size_t)(kb * 16 + r) * M + col0 + nc);
            bT[i][0] = f2tf(v.x); bT[i][1] = f2tf(v.y);
            bT[i][2] = f2tf(v.z); bT[i][3] = f2tf(v.w);
        }
    };
    auto store_regs = [&](int s) {
        #pragma unroll
        for (int i = 0; i < 2; i++) {
            int idx = tid + i * 256;
            int r   = idx >> 2;
            int kc  = (idx & 3) * 4;
            *(uint4*)&As[s][r][kc] = *(uint4*)aT[i];
        }
        #pragma unroll
        for (int i = 0; i < NBLD; i++) {
            int idx = tid + i * 256;
            int r, nc;
            if (BN == 128) { r = idx >> 5; nc = (idx & 31) * 4; }
            else           { r = idx >> 4; nc = (idx & 15) * 4; }
            *(uint4*)&Bs[s][r][nc] = *(uint4*)bT[i];
        }
    };

    load_regs(0);
    store_regs(0);
    __syncthreads();

    for (int kb = 0; kb < KB; kb++) {
        if (kb + 1 < KB) load_regs(kb + 1);   // LDG in flight over the mma burst
        const int s = kb & 1;

        #pragma unroll
        for (int kk = 0; kk < 2; kk++) {
            const int k8 = kk * 8;
            uint32_t a[2][4];
            #pragma unroll
            for (int mt = 0; mt < 2; mt++) {
                int mr = wm * 32 + mt * 16 + gi;
                a[mt][0] = __float_as_uint(As[s][mr    ][k8     + ci]);
                a[mt][1] = __float_as_uint(As[s][mr + 8][k8     + ci]);
                a[mt][2] = __float_as_uint(As[s][mr    ][k8 + 4 + ci]);
                a[mt][3] = __float_as_uint(As[s][mr + 8][k8 + 4 + ci]);
            }
            uint32_t b[NT][2];
            #pragma unroll
            for (int nt = 0; nt < NT; nt++) {
                int nc = wn * WN + nt * 8 + gi;
                b[nt][0] = __float_as_uint(Bs[s][k8     + ci][nc]);
                b[nt][1] = __float_as_uint(Bs[s][k8 + 4 + ci][nc]);
            }
            #pragma unroll
            for (int mt = 0; mt < 2; mt++)
                #pragma unroll
                for (int nt = 0; nt < NT; nt++)
                    mma_tf32(c[mt][nt], a[mt], b[nt]);
        }

        if (kb + 1 < KB) {
            store_regs((kb + 1) & 1);   // other buffer; prior sync guarantees readers done
            __syncthreads();
        }
    }

    // ---- epilogue: (+bias), (sigmoid), (dinv row pre-scale), store float2s
    #pragma unroll
    for (int mt = 0; mt < 2; mt++) {
        int r = row0 + wm * 32 + mt * 16 + gi;
        float d0s = 1.f, d1s = 1.f;
        if (DSC) {
            if (r < N)     d0s = g_dinv[r];
            if (r + 8 < N) d1s = g_dinv[r + 8];
        }
        #pragma unroll
        for (int nt = 0; nt < NT; nt++) {
            int gcol = col0 + wn * WN + nt * 8 + ci * 2;
            float b0 = 0.f, b1 = 0.f;
            if (BIAS) { b0 = __ldg(bias + gcol); b1 = __ldg(bias + gcol + 1); }
            float v0 = c[mt][nt][0] + b0, v1 = c[mt][nt][1] + b1;
            float v2 = c[mt][nt][2] + b0, v3 = c[mt][nt][3] + b1;
            if (SIG) {
                v0 = 1.f / (1.f + __expf(-v0));
                v1 = 1.f / (1.f + __expf(-v1));
                v2 = 1.f / (1.f + __expf(-v2));
                v3 = 1.f / (1.f + __expf(-v3));
            }
            if (DSC) { v0 *= d0s; v1 *= d0s; v2 *= d1s; v3 *= d1s; }
            if (r < N)
                *(float2*)(Out + (size_t)r * M + gcol) = make_float2(v0, v1);
            if (r + 8 < N)
                *(float2*)(Out + (size_t)(r + 8) * M + gcol) = make_float2(v2, v3);
        }
    }
}

// ---------------- aggregation (float4 lanes, 4-edge ILP) ---------------------
// PRE=false: out[i] = dinv_i*(Σ_r dinv_r*in[r] + dinv_i*in[i]) (+bias)
// PRE=true : rows already scaled by dinv -> out[i] = dinv_i*(Σ_r in[r] + in[i]) (+bias)
// SRCSEL: 0=g_bufA, 1=g_bufB, 2=external
template <int C, int SRCSEL, bool OUT_EXT, bool BIAS, bool PRE>
__global__ __launch_bounds__(128)
void k_agg(const float* __restrict__ in_ext, const float* __restrict__ bias,
           float* __restrict__ out_ext) {
    constexpr int T   = C / 4;       // threads per node
    constexpr int NPB = 128 / T;     // nodes per block
    const float* __restrict__ in =
        (SRCSEL == 2) ? in_ext
        : (SRCSEL == 0 ? (const float*)g_bufA : (const float*)g_bufB);
    float* __restrict__ out = OUT_EXT ? out_ext : (float*)g_bufA;

    const int node = blockIdx.x * NPB + threadIdx.x / T;
    if (node >= NN) return;
    const int c4 = (threadIdx.x % T) * 4;

    const float di = g_dinv[node];
    float4 s = __ldg((const float4*)(in + (size_t)node * C + c4));
    float ax, ay, az, aw;
    if (PRE) { ax = s.x;      ay = s.y;      az = s.z;      aw = s.w; }
    else     { ax = di * s.x; ay = di * s.y; az = di * s.z; aw = di * s.w; }

    int p = g_off[node];
    const int e = g_off[node + 1];
    for (; p + 3 < e; p += 4) {
        int r0 = g_csr[p],     r1 = g_csr[p + 1];
        int r2 = g_csr[p + 2], r3 = g_csr[p + 3];
        float4 v0 = __ldg((const float4*)(in + (size_t)r0 * C + c4));
        float4 v1 = __ldg((const float4*)(in + (size_t)r1 * C + c4));
        float4 v2 = __ldg((const float4*)(in + (size_t)r2 * C + c4));
        float4 v3 = __ldg((const float4*)(in + (size_t)r3 * C + c4));
        if (PRE) {
            ax += v0.x + v1.x + v2.x + v3.x;
            ay += v0.y + v1.y + v2.y + v3.y;
            az += v0.z + v1.z + v2.z + v3.z;
            aw += v0.w + v1.w + v2.w + v3.w;
        } else {
            float d0 = g_dinv[r0], d1 = g_dinv[r1];
            float d2 = g_dinv[r2], d3 = g_dinv[r3];
            ax += d0 * v0.x + d1 * v1.x + d2 * v2.x + d3 * v3.x;
            ay += d0 * v0.y + d1 * v1.y + d2 * v2.y + d3 * v3.y;
            az += d0 * v0.z + d1 * v1.z + d2 * v2.z + d3 * v3.z;
            aw += d0 * v0.w + d1 * v1.w + d2 * v2.w + d3 * v3.w;
        }
    }
    for (; p < e; p++) {
        int r = g_csr[p];
        float4 v = __ldg((const float4*)(in + (size_t)r * C + c4));
        if (PRE) {
            ax += v.x; ay += v.y; az += v.z; aw += v.w;
        } else {
            float d = g_dinv[r];
            ax += d * v.x; ay += d * v.y; az += d * v.z; aw += d * v.w;
        }
    }

    float4 o = make_float4(di * ax, di * ay, di * az, di * aw);
    if (BIAS) {
        float4 b = __ldg((const float4*)(bias + c4));
        o.x += b.x; o.y += b.y; o.z += b.z; o.w += b.w;
    }
    *(float4*)(out + (size_t)node * C + c4) = o;
}

// ---------------- launch: kernel launches ONLY -------------------------------
extern "C" void kernel_launch(void* const* d_in, const int* in_sizes, int n_in,
                              void* d_out, int out_size) {
    const float* x   = (const float*)d_in[0];
    // d_in[1] = edge_attr (unused by forward)
    const void*  ei  = d_in[2];
    const float* W1  = (const float*)d_in[3];
    const float* b1  = (const float*)d_in[4];
    const float* W2  = (const float*)d_in[5];
    const float* b2  = (const float*)d_in[6];
    const float* W3  = (const float*)d_in[7];
    const float* b3  = (const float*)d_in[8];
    float*       out = (float*)d_out;

    const int n = NN;
    const int e = in_sizes[2] / 2;             // 800000
    const int nblk = (n + 1023) / 1024;        // 49

    // ---- graph preprocessing
    k_zero_deg<<<(n + 255) / 256, 256>>>((const int*)ei, n);
    k_prep_edges<<<(e + 255) / 256, 256>>>(ei, e);
    k_scan<<<nblk, 1024>>>(n);
    k_fill_csr<<<(e + 255) / 256, 256>>>(ei, e);

    // ---- layer 1: aggregate x (128ch) -> bufA; GEMM+bias+sig (+dinv) -> bufB
    k_agg<C_IN, 2, false, false, false><<<NN / 4, 128>>>(x, nullptr, nullptr);
    {
        dim3 grid(C_HID / 128, (n + 127) / 128);
        k_gemm_tf32<128, false, false, true, true, true>
            <<<grid, 256>>>(W1, b1, n, C_IN, C_HID);
    }
    // ---- layer 2: aggregate pre-scaled bufB -> bufA; GEMM+bias+sig -> bufB
    k_agg<C_HID, 1, false, false, true><<<NN / 2, 128>>>(nullptr, nullptr, nullptr);
    {
        dim3 grid(C_HID / 128, (n + 127) / 128);
        k_gemm_tf32<128, false, false, true, true, false>
            <<<grid, 256>>>(W2, b2, n, C_HID, C_HID);
    }
    // ---- layer 3: GEMM bufB @ W3 (+dinv) -> bufA; aggregate + bias -> out
    {
        dim3 grid(C_OUT / 64, (n + 127) / 128);
        k_gemm_tf32<64, true, true, false, false, true>
            <<<grid, 256>>>(W3, nullptr, n, C_HID, C_OUT);
    }
    k_agg<C_OUT, 0, true, true, true><<<NN / 8, 128>>>(nullptr, b3, out);
}

// round 13
// speedup vs baseline: 1.1436x; 1.0807x over previous
#include <cuda_runtime.h>
#include <cuda_bf16.h>
#include <cuda_fp16.h>
#include <math.h>
#include <stdint.h>

// Problem constants (fixed by the dataset)
#define NN    50000     // nodes
#define EE    800000    // edges
#define C_IN  128
#define C_HID 256
#define C_OUT 64

// ---------------- scratch (device globals; no allocation, no host API) -----
__device__ int    g_is64;           // 1 if edge_index delivered as int64
__device__ int    g_deg[NN];
__device__ float  g_dinv[NN];
__device__ int    g_off[NN + 1];
__device__ int    g_cursor[NN];
__device__ int    g_csr[EE];
__device__ unsigned long long g_pkt[64];  // lookback packets: value<<2 | flag
__device__ float  g_bufA[(size_t)NN * C_HID];   // fp32 agg outputs (GEMM inputs)
__device__ float  g_bufB[(size_t)NN * C_HID];   // fp32 GEMM2 output
__device__ __half g_bufH[(size_t)NN * C_HID];   // fp16 dinv-prescaled features

// ---------------- prep ------------------------------------------------------
__global__ void k_zero_deg(const int* __restrict__ ei32, int n) {
    int i = blockIdx.x * blockDim.x + threadIdx.x;
    if (i < n) g_deg[i] = 0;
    if (i < 64) g_pkt[i] = 0ULL;
    if (blockIdx.x == 0 && threadIdx.x == 0) {
        int all_zero = 1;
        #pragma unroll
        for (int k = 0; k < 64; k++)
            if (ei32[2 * k + 1] != 0) all_zero = 0;
        g_is64 = all_zero;
    }
}

// degree count only (reads just the col half of edge_index)
__global__ void k_prep_edges(const void* __restrict__ ei, int e) {
    int idx = blockIdx.x * blockDim.x + threadIdx.x;
    if (idx >= e) return;
    int c;
    if (g_is64) c = (int)((const long long*)ei)[(size_t)e + idx];
    else        c = ((const int*)ei)[(size_t)e + idx];
    atomicAdd(&g_deg[c], 1);
}

// single-pass decoupled-lookback scan: g_deg -> g_off/g_cursor, dinv fused.
__global__ void k_scan(int n) {
    __shared__ int wsum[32];
    __shared__ int s_excl;
    const int b = blockIdx.x;
    const int i = b * 1024 + threadIdx.x;
    const int v = (i < n) ? g_deg[i] : 0;
    const int lane = threadIdx.x & 31, w = threadIdx.x >> 5;

    int s = v;
    #pragma unroll
    for (int d = 1; d < 32; d <<= 1) {
        int t = __shfl_up_sync(~0u, s, d);
        if (lane >= d) s += t;
    }
    if (lane == 31) wsum[w] = s;
    __syncthreads();
    if (w == 0) {
        int ws = wsum[lane];
        #pragma unroll
        for (int d = 1; d < 32; d <<= 1) {
            int t = __shfl_up_sync(~0u, ws, d);
            if (lane >= d) ws += t;
        }
        wsum[lane] = ws;
    }
    __syncthreads();
    const int excl = s - v + (w > 0 ? wsum[w - 1] : 0);
    const int btotal = wsum[31];

    if (threadIdx.x == 0) {
        int ex = 0;
        if (b == 0) {
            atomicExch(&g_pkt[0], ((unsigned long long)btotal << 2) | 2ULL);
        } else {
            atomicExch(&g_pkt[b], ((unsigned long long)btotal << 2) | 1ULL);
            for (int j = b - 1; j >= 0;) {
                unsigned long long p;
                do { p = atomicAdd(&g_pkt[j], 0ULL); } while ((p & 3ULL) == 0ULL);
                ex += (int)(p >> 2);
                if ((p & 3ULL) == 2ULL) break;
                j--;
            }
            atomicExch(&g_pkt[b], ((unsigned long long)(ex + btotal) << 2) | 2ULL);
        }
        s_excl = ex;
    }
    __syncthreads();

    const int off = s_excl + excl;
    if (i < n) {
        g_off[i] = off;
        g_cursor[i] = off;
        g_dinv[i] = rsqrtf((float)(v + 1));
    }
    if (i == n - 1) g_off[n] = off + v;
}

__global__ void k_fill_csr(const void* __restrict__ ei, int e) {
    int idx = blockIdx.x * blockDim.x + threadIdx.x;
    if (idx >= e) return;
    int r, c;
    if (g_is64) {
        const long long* p = (const long long*)ei;
        r = (int)p[idx];
        c = (int)p[(size_t)e + idx];
    } else {
        const int* p = (const int*)ei;
        r = p[idx];
        c = p[(size_t)e + idx];
    }
    int pos = atomicAdd(&g_cursor[c], 1);
    g_csr[pos] = r;
}

// x (fp32, 128ch) -> g_bufH as dinv-prescaled fp16
__global__ void k_x2h(const float* __restrict__ x) {
    int i = blockIdx.x * 256 + threadIdx.x;       // 8 elements per thread
    if (i >= NN * (C_IN / 8)) return;
    int node = i / (C_IN / 8);
    float d = g_dinv[node];
    const float4* p = (const float4*)x + (size_t)i * 2;
    float4 a = __ldg(p), b = __ldg(p + 1);
    __half2 h0 = __floats2half2_rn(d * a.x, d * a.y);
    __half2 h1 = __floats2half2_rn(d * a.z, d * a.w);
    __half2 h2 = __floats2half2_rn(d * b.x, d * b.y);
    __half2 h3 = __floats2half2_rn(d * b.z, d * b.w);
    uint4 o;
    o.x = *(uint32_t*)&h0; o.y = *(uint32_t*)&h1;
    o.z = *(uint32_t*)&h2; o.w = *(uint32_t*)&h3;
    ((uint4*)g_bufH)[i] = o;
}

// ---------------- tf32 helpers ----------------------------------------------
__device__ __forceinline__ uint32_t f2tf(float f) {
    uint32_t u;
    asm("cvt.rna.tf32.f32 %0, %1;" : "=r"(u) : "f"(f));
    return u;
}

__device__ __forceinline__ void mma_tf32(float c[4], const uint32_t a[4],
                                         const uint32_t b[2]) {
    asm volatile(
        "mma.sync.aligned.m16n8k8.row.col.f32.tf32.tf32.f32 "
        "{%0,%1,%2,%3}, {%4,%5,%6,%7}, {%8,%9}, {%0,%1,%2,%3};"
        : "+f"(c[0]), "+f"(c[1]), "+f"(c[2]), "+f"(c[3])
        : "r"(a[0]), "r"(a[1]), "r"(a[2]), "r"(a[3]), "r"(b[0]), "r"(b[1]));
}

// ---------------- tf32 GEMM: Out[N,M] = A[N,K] @ W[K,M] ----------------------
// (+bias, +sigmoid, optional dinv row pre-scale)
// DSTSEL: 0 = g_bufA (fp32), 1 = g_bufB (fp32), 2 = g_bufH (fp16)
template <int BN, bool SRC_B, int DSTSEL, bool SIG, bool BIAS, bool DSC>
__global__ __launch_bounds__(256)
void k_gemm_tf32(const float* __restrict__ W, const float* __restrict__ bias,
                 int N, int K, int M) {
    const float* __restrict__ A = SRC_B ? (const float*)g_bufB : (const float*)g_bufA;
    float* __restrict__ OutF = (DSTSEL == 0) ? (float*)g_bufA : (float*)g_bufB;
    __half* __restrict__ OutH = (__half*)g_bufH;

    constexpr int WN   = BN / 2;               // warp tile N
    constexpr int NT   = WN / 8;               // m16n8 tiles per warp
    constexpr int NBLD = (BN == 128) ? 2 : 1;  // B float4 loads per thread/stage

    __shared__ __align__(16) float As[2][128][20];     // conflict-free strides
    __shared__ __align__(16) float Bs[2][16][BN + 8];

    const int tid  = threadIdx.x;
    const int lane = tid & 31;
    const int warp = tid >> 5;
    const int wm   = warp >> 1;
    const int wn   = warp & 1;
    const int gi   = lane >> 2;
    const int ci   = lane & 3;
    const int row0 = blockIdx.y * 128;
    const int col0 = blockIdx.x * BN;

    float c[2][NT][4];
    #pragma unroll
    for (int mt = 0; mt < 2; mt++)
        #pragma unroll
        for (int nt = 0; nt < NT; nt++)
            #pragma unroll
            for (int j = 0; j < 4; j++) c[mt][nt][j] = 0.f;

    uint32_t aT[2][4];
    uint32_t bT[NBLD][4];
    const int KB = K / 16;

    auto load_regs = [&](int kb) {
        #pragma unroll
        for (int i = 0; i < 2; i++) {
            int idx = tid + i * 256;
            int r   = idx >> 2;
            int kc  = (idx & 3) * 4;
            float4 v = make_float4(0.f, 0.f, 0.f, 0.f);
            if (row0 + r < N)
                v = *(const float4*)(A + (size_t)(row0 + r) * K + kb * 16 + kc);
            aT[i][0] = f2tf(v.x); aT[i][1] = f2tf(v.y);
            aT[i][2] = f2tf(v.z); aT[i][3] = f2tf(v.w);
        }
        #pragma unroll
        for (int i = 0; i < NBLD; i++) {
            int idx = tid + i * 256;
            int r, nc;
            if (BN == 128) { r = idx >> 5; nc = (idx & 31) * 4; }
            else           { r = idx >> 4; nc = (idx & 15) * 4; }
            float4 v = *(const float4*)(W + (size_t)(kb * 16 + r) * M + col0 + nc);
            bT[i][0] = f2tf(v.x); bT[i][1] = f2tf(v.y);
            bT[i][2] = f2tf(v.z); bT[i][3] = f2tf(v.w);
        }
    };
    auto store_regs = [&](int s) {
        #pragma unroll
        for (int i = 0; i < 2; i++) {
            int idx = tid + i * 256;
            int r   = idx >> 2;
            int kc  = (idx & 3) * 4;
            *(uint4*)&As[s][r][kc] = *(uint4*)aT[i];
        }
        #pragma unroll
        for (int i = 0; i < NBLD; i++) {
            int idx = tid + i * 256;
            int r, nc;
            if (BN == 128) { r = idx >> 5; nc = (idx & 31) * 4; }
            else           { r = idx >> 4; nc = (idx & 15) * 4; }
            *(uint4*)&Bs[s][r][nc] = *(uint4*)bT[i];
        }
    };

    load_regs(0);
    store_regs(0);
    __syncthreads();

    for (int kb = 0; kb < KB; kb++) {
        if (kb + 1 < KB) load_regs(kb + 1);
        const int s = kb & 1;

        #pragma unroll
        for (int kk = 0; kk < 2; kk++) {
            const int k8 = kk * 8;
            uint32_t a[2][4];
            #pragma unroll
            for (int mt = 0; mt < 2; mt++) {
                int mr = wm * 32 + mt * 16 + gi;
                a[mt][0] = __float_as_uint(As[s][mr    ][k8     + ci]);
                a[mt][1] = __float_as_uint(As[s][mr + 8][k8     + ci]);
                a[mt][2] = __float_as_uint(As[s][mr    ][k8 + 4 + ci]);
                a[mt][3] = __float_as_uint(As[s][mr + 8][k8 + 4 + ci]);
            }
            uint32_t b[NT][2];
            #pragma unroll
            for (int nt = 0; nt < NT; nt++) {
                int nc = wn * WN + nt * 8 + gi;
                b[nt][0] = __float_as_uint(Bs[s][k8     + ci][nc]);
                b[nt][1] = __float_as_uint(Bs[s][k8 + 4 + ci][nc]);
            }
            #pragma unroll
            for (int mt = 0; mt < 2; mt++)
                #pragma unroll
                for (int nt = 0; nt < NT; nt++)
                    mma_tf32(c[mt][nt], a[mt], b[nt]);
        }

        if (kb + 1 < KB) {
            store_regs((kb + 1) & 1);
            __syncthreads();
        }
    }

    // ---- epilogue
    #pragma unroll
    for (int mt = 0; mt < 2; mt++) {
        int r = row0 + wm * 32 + mt * 16 + gi;
        float d0s = 1.f, d1s = 1.f;
        if (DSC) {
            if (r < N)     d0s = g_dinv[r];
            if (r + 8 < N) d1s = g_dinv[r + 8];
        }
        #pragma unroll
        for (int nt = 0; nt < NT; nt++) {
            int gcol = col0 + wn * WN + nt * 8 + ci * 2;
            float b0 = 0.f, b1 = 0.f;
            if (BIAS) { b0 = __ldg(bias + gcol); b1 = __ldg(bias + gcol + 1); }
            float v0 = c[mt][nt][0] + b0, v1 = c[mt][nt][1] + b1;
            float v2 = c[mt][nt][2] + b0, v3 = c[mt][nt][3] + b1;
            if (SIG) {
                v0 = 1.f / (1.f + __expf(-v0));
                v1 = 1.f / (1.f + __expf(-v1));
                v2 = 1.f / (1.f + __expf(-v2));
                v3 = 1.f / (1.f + __expf(-v3));
            }
            if (DSC) { v0 *= d0s; v1 *= d0s; v2 *= d1s; v3 *= d1s; }
            if (DSTSEL == 2) {
                if (r < N)
                    *(__half2*)(OutH + (size_t)r * M + gcol) =
                        __floats2half2_rn(v0, v1);
                if (r + 8 < N)
                    *(__half2*)(OutH + (size_t)(r + 8) * M + gcol) =
                        __floats2half2_rn(v2, v3);
            } else {
                if (r < N)
                    *(float2*)(OutF + (size_t)r * M + gcol) = make_float2(v0, v1);
                if (r + 8 < N)
                    *(float2*)(OutF + (size_t)(r + 8) * M + gcol) = make_float2(v2, v3);
            }
        }
    }
}

// ---------------- fp16 aggregation (8 halves/thread, 4-edge ILP) -------------
// rows in g_bufH are dinv-prescaled: out[i] = dinv_i*(Σ_r in[r] + in[i]) (+bias)
__device__ __forceinline__ void acc8(float ac[8], uint4 v) {
    float2 f0 = __half22float2(*reinterpret_cast<__half2*>(&v.x));
    float2 f1 = __half22float2(*reinterpret_cast<__half2*>(&v.y));
    float2 f2 = __half22float2(*reinterpret_cast<__half2*>(&v.z));
    float2 f3 = __half22float2(*reinterpret_cast<__half2*>(&v.w));
    ac[0] += f0.x; ac[1] += f0.y; ac[2] += f1.x; ac[3] += f1.y;
    ac[4] += f2.x; ac[5] += f2.y; ac[6] += f3.x; ac[7] += f3.y;
}

template <int C, bool OUT_EXT, bool BIAS>
__global__ __launch_bounds__(128)
void k_aggh(const float* __restrict__ bias, float* __restrict__ out_ext) {
    constexpr int T   = C / 8;       // threads per node
    constexpr int NPB = 128 / T;     // nodes per block
    const __half* __restrict__ in = (const __half*)g_bufH;
    float* __restrict__ out = OUT_EXT ? out_ext : (float*)g_bufA;

    const int node = blockIdx.x * NPB + threadIdx.x / T;
    if (node >= NN) return;
    const int c8 = (threadIdx.x % T) * 8;
    const float di = g_dinv[node];

    float ac[8] = {0.f, 0.f, 0.f, 0.f, 0.f, 0.f, 0.f, 0.f};
    acc8(ac, __ldg((const uint4*)(in + (size_t)node * C + c8)));   // self term

    int p = g_off[node];
    const int e = g_off[node + 1];
    for (; p + 3 < e; p += 4) {
        int r0 = g_csr[p],     r1 = g_csr[p + 1];
        int r2 = g_csr[p + 2], r3 = g_csr[p + 3];
        uint4 v0 = __ldg((const uint4*)(in + (size_t)r0 * C + c8));
        uint4 v1 = __ldg((const uint4*)(in + (size_t)r1 * C + c8));
        uint4 v2 = __ldg((const uint4*)(in + (size_t)r2 * C + c8));
        uint4 v3 = __ldg((const uint4*)(in + (size_t)r3 * C + c8));
        acc8(ac, v0); acc8(ac, v1); acc8(ac, v2); acc8(ac, v3);
    }
    for (; p < e; p++)
        acc8(ac, __ldg((const uint4*)(in + (size_t)g_csr[p] * C + c8)));

    float4 o0 = make_float4(di * ac[0], di * ac[1], di * ac[2], di * ac[3]);
    float4 o1 = make_float4(di * ac[4], di * ac[5], di * ac[6], di * ac[7]);
    if (BIAS) {
        float4 b0 = __ldg((const float4*)(bias + c8));
        float4 b1 = __ldg((const float4*)(bias + c8 + 4));
        o0.x += b0.x; o0.y += b0.y; o0.z += b0.z; o0.w += b0.w;
        o1.x += b1.x; o1.y += b1.y; o1.z += b1.z; o1.w += b1.w;
    }
    *(float4*)(out + (size_t)node * C + c8)     = o0;
    *(float4*)(out + (size_t)node * C + c8 + 4) = o1;
}

// ---------------- launch: kernel launches ONLY -------------------------------
extern "C" void kernel_launch(void* const* d_in, const int* in_sizes, int n_in,
                              void* d_out, int out_size) {
    const float* x   = (const float*)d_in[0];
    // d_in[1] = edge_attr (unused by forward)
    const void*  ei  = d_in[2];
    const float* W1  = (const float*)d_in[3];
    const float* b1  = (const float*)d_in[4];
    const float* W2  = (const float*)d_in[5];
    const float* b2  = (const float*)d_in[6];
    const float* W3  = (const float*)d_in[7];
    const float* b3  = (const float*)d_in[8];
    float*       out = (float*)d_out;

    const int n = NN;
    const int e = in_sizes[2] / 2;             // 800000
    const int nblk = (n + 1023) / 1024;        // 49

    // ---- graph preprocessing
    k_zero_deg<<<(n + 255) / 256, 256>>>((const int*)ei, n);
    k_prep_edges<<<(e + 255) / 256, 256>>>(ei, e);
    k_scan<<<nblk, 1024>>>(n);
    k_fill_csr<<<(e + 255) / 256, 256>>>(ei, e);
    k_x2h<<<(NN * (C_IN / 8) + 255) / 256, 256>>>(x);

    // ---- layer 1: agg fp16 x (128ch) -> bufA; GEMM+bias+sig+dinv -> bufH fp16
    k_aggh<C_IN, false, false><<<NN / 8, 128>>>(nullptr, nullptr);
    {
        dim3 grid(C_HID / 128, (n + 127) / 128);
        k_gemm_tf32<128, false, 2, true, true, true>
            <<<grid, 256>>>(W1, b1, n, C_IN, C_HID);
    }
    // ---- layer 2: agg fp16 bufH (256ch) -> bufA; GEMM+bias+sig -> bufB fp32
    k_aggh<C_HID, false, false><<<NN / 4, 128>>>(nullptr, nullptr);
    {
        dim3 grid(C_HID / 128, (n + 127) / 128);
        k_gemm_tf32<128, false, 1, true, true, false>
            <<<grid, 256>>>(W2, b2, n, C_HID, C_HID);
    }
    // ---- layer 3: GEMM bufB @ W3 +dinv -> bufH fp16; agg + bias -> out
    {
        dim3 grid(C_OUT / 64, (n + 127) / 128);
        k_gemm_tf32<64, true, 2, false, false, true>
            <<<grid, 256>>>(W3, nullptr, n, C_HID, C_OUT);
    }
    k_aggh<C_OUT, true, true><<<NN / 16, 128>>>(b3, out);
}

// round 14
// speedup vs baseline: 1.4449x; 1.2634x over previous
#include <cuda_runtime.h>
#include <cuda_bf16.h>
#include <cuda_fp16.h>
#include <math.h>
#include <stdint.h>

// Problem constants (fixed by the dataset)
#define NN    50000     // nodes
#define EE    800000    // edges
#define C_IN  128
#define C_HID 256
#define C_OUT 64

// ---------------- scratch (device globals; no allocation, no host API) -----
__device__ int    g_is64;           // 1 if edge_index delivered as int64
__device__ int    g_deg[NN];
__device__ float  g_dinv[NN];
__device__ int    g_off[NN + 1];
__device__ int    g_cursor[NN];
__device__ int    g_csr[EE];
__device__ unsigned long long g_pkt[64];  // lookback packets: value<<2 | flag
__device__ __half g_H1[(size_t)NN * C_HID];   // fp16 feature ping
__device__ __half g_H2[(size_t)NN * C_HID];   // fp16 feature pong
__device__ __half g_W1h[256 * 128];   // W1^T fp16 [M][K]
__device__ __half g_W2h[256 * 256];   // W2^T
__device__ __half g_W3h[64 * 256];    // W3^T

// ---------------- prep ------------------------------------------------------
__global__ void k_zero_deg(const int* __restrict__ ei32, int n) {
    int i = blockIdx.x * blockDim.x + threadIdx.x;
    if (i < n) g_deg[i] = 0;
    if (i < 64) g_pkt[i] = 0ULL;
    if (blockIdx.x == 0 && threadIdx.x == 0) {
        int all_zero = 1;
        #pragma unroll
        for (int k = 0; k < 64; k++)
            if (ei32[2 * k + 1] != 0) all_zero = 0;
        g_is64 = all_zero;
    }
}

__global__ void k_prep_edges(const void* __restrict__ ei, int e) {
    int idx = blockIdx.x * blockDim.x + threadIdx.x;
    if (idx >= e) return;
    int c;
    if (g_is64) c = (int)((const long long*)ei)[(size_t)e + idx];
    else        c = ((const int*)ei)[(size_t)e + idx];
    atomicAdd(&g_deg[c], 1);
}

// single-pass decoupled-lookback scan: g_deg -> g_off/g_cursor, dinv fused.
__global__ void k_scan(int n) {
    __shared__ int wsum[32];
    __shared__ int s_excl;
    const int b = blockIdx.x;
    const int i = b * 1024 + threadIdx.x;
    const int v = (i < n) ? g_deg[i] : 0;
    const int lane = threadIdx.x & 31, w = threadIdx.x >> 5;

    int s = v;
    #pragma unroll
    for (int d = 1; d < 32; d <<= 1) {
        int t = __shfl_up_sync(~0u, s, d);
        if (lane >= d) s += t;
    }
    if (lane == 31) wsum[w] = s;
    __syncthreads();
    if (w == 0) {
        int ws = wsum[lane];
        #pragma unroll
        for (int d = 1; d < 32; d <<= 1) {
            int t = __shfl_up_sync(~0u, ws, d);
            if (lane >= d) ws += t;
        }
        wsum[lane] = ws;
    }
    __syncthreads();
    const int excl = s - v + (w > 0 ? wsum[w - 1] : 0);
    const int btotal = wsum[31];

    if (threadIdx.x == 0) {
        int ex = 0;
        if (b == 0) {
            atomicExch(&g_pkt[0], ((unsigned long long)btotal << 2) | 2ULL);
        } else {
            atomicExch(&g_pkt[b], ((unsigned long long)btotal << 2) | 1ULL);
            for (int j = b - 1; j >= 0;) {
                unsigned long long p;
                do { p = atomicAdd(&g_pkt[j], 0ULL); } while ((p & 3ULL) == 0ULL);
                ex += (int)(p >> 2);
                if ((p & 3ULL) == 2ULL) break;
                j--;
            }
            atomicExch(&g_pkt[b], ((unsigned long long)(ex + btotal) << 2) | 2ULL);
        }
        s_excl = ex;
    }
    __syncthreads();

    const int off = s_excl + excl;
    if (i < n) {
        g_off[i] = off;
        g_cursor[i] = off;
        g_dinv[i] = rsqrtf((float)(v + 1));
    }
    if (i == n - 1) g_off[n] = off + v;
}

__global__ void k_fill_csr(const void* __restrict__ ei, int e) {
    int idx = blockIdx.x * blockDim.x + threadIdx.x;
    if (idx >= e) return;
    int r, c;
    if (g_is64) {
        const long long* p = (const long long*)ei;
        r = (int)p[idx];
        c = (int)p[(size_t)e + idx];
    } else {
        const int* p = (const int*)ei;
        r = p[idx];
        c = p[(size_t)e + idx];
    }
    int pos = atomicAdd(&g_cursor[c], 1);
    g_csr[pos] = r;
}

// x (fp32, 128ch) -> g_H1 as dinv-prescaled fp16
__global__ void k_x2h(const float* __restrict__ x) {
    int i = blockIdx.x * 256 + threadIdx.x;       // 8 elements per thread
    if (i >= NN * (C_IN / 8)) return;
    int node = i / (C_IN / 8);
    float d = g_dinv[node];
    const float4* p = (const float4*)x + (size_t)i * 2;
    float4 a = __ldg(p), b = __ldg(p + 1);
    __half2 h0 = __floats2half2_rn(d * a.x, d * a.y);
    __half2 h1 = __floats2half2_rn(d * a.z, d * a.w);
    __half2 h2 = __floats2half2_rn(d * b.x, d * b.y);
    __half2 h3 = __floats2half2_rn(d * b.z, d * b.w);
    uint4 o;
    o.x = *(uint32_t*)&h0; o.y = *(uint32_t*)&h1;
    o.z = *(uint32_t*)&h2; o.w = *(uint32_t*)&h3;
    ((uint4*)g_H1)[i] = o;
}

// W [K][M] fp32 -> Wt [M][K] fp16 (transpose + convert)
template <int WSEL>
__global__ void k_w2h(const float* __restrict__ W, int K, int M) {
    __shared__ float t[32][33];
    __half* dst = (WSEL == 0) ? g_W1h : ((WSEL == 1) ? g_W2h : g_W3h);
    int m0 = blockIdx.x * 32, k0 = blockIdx.y * 32;
    #pragma unroll
    for (int i = threadIdx.y; i < 32; i += 8)
        t[threadIdx.x][i] = W[(size_t)(k0 + i) * M + m0 + threadIdx.x];
    __syncthreads();
    #pragma unroll
    for (int i = threadIdx.y; i < 32; i += 8)
        dst[(size_t)(m0 + i) * K + k0 + threadIdx.x] = __float2half(t[i][threadIdx.x]);
}

// ---------------- fp16 HMMA helper (m16n8k16, fp32 accum) ---------------------
__device__ __forceinline__ void mma_f16(float c[4], const uint32_t a[4],
                                        const uint32_t b[2]) {
    asm volatile(
        "mma.sync.aligned.m16n8k16.row.col.f32.f16.f16.f32 "
        "{%0,%1,%2,%3}, {%4,%5,%6,%7}, {%8,%9}, {%0,%1,%2,%3};"
        : "+f"(c[0]), "+f"(c[1]), "+f"(c[2]), "+f"(c[3])
        : "r"(a[0]), "r"(a[1]), "r"(a[2]), "r"(a[3]), "r"(b[0]), "r"(b[1]));
}

// ---------------- fp16 GEMM: Out[N,M] = A[N,K] @ W[K,M] ----------------------
// A fp16 [N][K] (H1/H2), Wt fp16 [M][K] pre-transposed. BM=128, BK=32,
// double-buffered. 256 threads (8 warps 4x2), warp tile 32 x (BN/2).
// smem rows stride 40 halves (20 half2): gi*20+ci is a bank permutation.
// SRC/DST: 1 = g_H1, 2 = g_H2.  (+bias, +sigmoid, +dinv row pre-scale)
template <int BN, int WSEL, int SRC, int DST, bool SIG, bool BIAS, bool DSC>
__global__ __launch_bounds__(256)
void k_gemm_f16(const float* __restrict__ bias, int N, int K, int M) {
    const __half* __restrict__ A = (SRC == 1) ? (const __half*)g_H1
                                              : (const __half*)g_H2;
    __half* __restrict__ Out = (DST == 1) ? (__half*)g_H1 : (__half*)g_H2;
    const __half* __restrict__ Wt =
        (WSEL == 0) ? g_W1h : ((WSEL == 1) ? g_W2h : g_W3h);

    constexpr int WN   = BN / 2;               // warp tile N
    constexpr int NT   = WN / 8;               // m16n8 tiles per warp
    constexpr int NBLD = (BN == 128) ? 2 : 1;  // B uint4 loads per thread/stage

    // half2-unit arrays; row stride 20 half2 (= 40 halves = 80B)
    __shared__ __align__(16) uint32_t As[2][128 * 20];
    __shared__ __align__(16) uint32_t Bs[2][BN * 20];

    const int tid  = threadIdx.x;
    const int lane = tid & 31;
    const int warp = tid >> 5;
    const int wm   = warp >> 1;
    const int wn   = warp & 1;
    const int gi   = lane >> 2;
    const int ci   = lane & 3;
    const int row0 = blockIdx.y * 128;
    const int col0 = blockIdx.x * BN;

    float c[2][NT][4];
    #pragma unroll
    for (int mt = 0; mt < 2; mt++)
        #pragma unroll
        for (int nt = 0; nt < NT; nt++)
            #pragma unroll
            for (int j = 0; j < 4; j++) c[mt][nt][j] = 0.f;

    uint4 aR[2], bR[NBLD];
    const int KB = K / 32;

    auto load_regs = [&](int kb) {
        #pragma unroll
        for (int i = 0; i < 2; i++) {
            int idx = tid + i * 256;
            int r = idx >> 2, s = idx & 3;       // 4 uint4 (8 halves) per 32-row
            aR[i] = make_uint4(0u, 0u, 0u, 0u);
            if (row0 + r < N)
                aR[i] = *(const uint4*)(A + (size_t)(row0 + r) * K + kb * 32 + s * 8);
        }
        #pragma unroll
        for (int i = 0; i < NBLD; i++) {
            int idx = tid + i * 256;
            int r = idx >> 2, s = idx & 3;
            bR[i] = *(const uint4*)(Wt + (size_t)(col0 + r) * K + kb * 32 + s * 8);
        }
    };
    auto store_regs = [&](int st) {
        #pragma unroll
        for (int i = 0; i < 2; i++) {
            int idx = tid + i * 256;
            int r = idx >> 2, s = idx & 3;
            *(uint4*)&As[st][r * 20 + s * 4] = aR[i];
        }
        #pragma unroll
        for (int i = 0; i < NBLD; i++) {
            int idx = tid + i * 256;
            int r = idx >> 2, s = idx & 3;
            *(uint4*)&Bs[st][r * 20 + s * 4] = bR[i];
        }
    };

    load_regs(0);
    store_regs(0);
    __syncthreads();

    for (int kb = 0; kb < KB; kb++) {
        if (kb + 1 < KB) load_regs(kb + 1);   // LDG in flight over the mma burst
        const int st = kb & 1;

        #pragma unroll
        for (int kk = 0; kk < 2; kk++) {      // two k16 steps per BK=32
            const int kbase = kk * 8 + ci;    // half2 index within row
            uint32_t a[2][4];
            #pragma unroll
            for (int mt = 0; mt < 2; mt++) {
                int mr = wm * 32 + mt * 16 + gi;
                a[mt][0] = As[st][mr * 20       + kbase];
                a[mt][1] = As[st][(mr + 8) * 20 + kbase];
                a[mt][2] = As[st][mr * 20       + kbase + 4];
                a[mt][3] = As[st][(mr + 8) * 20 + kbase + 4];
            }
            uint32_t b[NT][2];
            #pragma unroll
            for (int nt = 0; nt < NT; nt++) {
                int nc = wn * WN + nt * 8 + gi;
                b[nt][0] = Bs[st][nc * 20 + kbase];
                b[nt][1] = Bs[st][nc * 20 + kbase + 4];
            }
            #pragma unroll
            for (int mt = 0; mt < 2; mt++)
                #pragma unroll
                for (int nt = 0; nt < NT; nt++)
                    mma_f16(c[mt][nt], a[mt], b[nt]);
        }

        if (kb + 1 < KB) {
            store_regs((kb + 1) & 1);
            __syncthreads();
        }
    }

    // ---- epilogue: (+bias), (sigmoid), (dinv), store half2 pairs
    #pragma unroll
    for (int mt = 0; mt < 2; mt++) {
        int r = row0 + wm * 32 + mt * 16 + gi;
        float d0s = 1.f, d1s = 1.f;
        if (DSC) {
            if (r < N)     d0s = g_dinv[r];
            if (r + 8 < N) d1s = g_dinv[r + 8];
        }
        #pragma unroll
        for (int nt = 0; nt < NT; nt++) {
            int gcol = col0 + wn * WN + nt * 8 + ci * 2;
            float b0 = 0.f, b1 = 0.f;
            if (BIAS) { b0 = __ldg(bias + gcol); b1 = __ldg(bias + gcol + 1); }
            float v0 = c[mt][nt][0] + b0, v1 = c[mt][nt][1] + b1;
            float v2 = c[mt][nt][2] + b0, v3 = c[mt][nt][3] + b1;
            if (SIG) {
                v0 = 1.f / (1.f + __expf(-v0));
                v1 = 1.f / (1.f + __expf(-v1));
                v2 = 1.f / (1.f + __expf(-v2));
                v3 = 1.f / (1.f + __expf(-v3));
            }
            if (DSC) { v0 *= d0s; v1 *= d0s; v2 *= d1s; v3 *= d1s; }
            if (r < N)
                *(__half2*)(Out + (size_t)r * M + gcol) = __floats2half2_rn(v0, v1);
            if (r + 8 < N)
                *(__half2*)(Out + (size_t)(r + 8) * M + gcol) = __floats2half2_rn(v2, v3);
        }
    }
}

// ---------------- fp16 aggregation (8 halves/thread, 4-edge ILP) -------------
// rows prescaled by dinv: out[i] = dinv_i*(Σ_r in[r] + in[i]) (+bias)
// SRC: 1/2 = H1/H2.  DST: 0 = external fp32 out, 1/2 = H1/H2 fp16.
__device__ __forceinline__ void acc8(float ac[8], uint4 v) {
    float2 f0 = __half22float2(*reinterpret_cast<__half2*>(&v.x));
    float2 f1 = __half22float2(*reinterpret_cast<__half2*>(&v.y));
    float2 f2 = __half22float2(*reinterpret_cast<__half2*>(&v.z));
    float2 f3 = __half22float2(*reinterpret_cast<__half2*>(&v.w));
    ac[0] += f0.x; ac[1] += f0.y; ac[2] += f1.x; ac[3] += f1.y;
    ac[4] += f2.x; ac[5] += f2.y; ac[6] += f3.x; ac[7] += f3.y;
}

template <int C, int SRC, int DST, bool BIAS>
__global__ __launch_bounds__(128)
void k_aggh(const float* __restrict__ bias, float* __restrict__ out_ext) {
    constexpr int T   = C / 8;       // threads per node
    constexpr int NPB = 128 / T;     // nodes per block
    const __half* __restrict__ in = (SRC == 1) ? (const __half*)g_H1
                                               : (const __half*)g_H2;

    const int node = blockIdx.x * NPB + threadIdx.x / T;
    if (node >= NN) return;
    const int c8 = (threadIdx.x % T) * 8;
    const float di = g_dinv[node];

    float ac[8] = {0.f, 0.f, 0.f, 0.f, 0.f, 0.f, 0.f, 0.f};
    acc8(ac, __ldg((const uint4*)(in + (size_t)node * C + c8)));   // self term

    int p = g_off[node];
    const int e = g_off[node + 1];
    for (; p + 3 < e; p += 4) {
        int r0 = g_csr[p],     r1 = g_csr[p + 1];
        int r2 = g_csr[p + 2], r3 = g_csr[p + 3];
        uint4 v0 = __ldg((const uint4*)(in + (size_t)r0 * C + c8));
        uint4 v1 = __ldg((const uint4*)(in + (size_t)r1 * C + c8));
        uint4 v2 = __ldg((const uint4*)(in + (size_t)r2 * C + c8));
        uint4 v3 = __ldg((const uint4*)(in + (size_t)r3 * C + c8));
        acc8(ac, v0); acc8(ac, v1); acc8(ac, v2); acc8(ac, v3);
    }
    for (; p < e; p++)
        acc8(ac, __ldg((const uint4*)(in + (size_t)g_csr[p] * C + c8)));

    if (DST == 0) {
        float4 o0 = make_float4(di * ac[0], di * ac[1], di * ac[2], di * ac[3]);
        float4 o1 = make_float4(di * ac[4], di * ac[5], di * ac[6], di * ac[7]);
        if (BIAS) {
            float4 b0 = __ldg((const float4*)(bias + c8));
            float4 b1 = __ldg((const float4*)(bias + c8 + 4));
            o0.x += b0.x; o0.y += b0.y; o0.z += b0.z; o0.w += b0.w;
            o1.x += b1.x; o1.y += b1.y; o1.z += b1.z; o1.w += b1.w;
        }
        *(float4*)(out_ext + (size_t)node * C + c8)     = o0;
        *(float4*)(out_ext + (size_t)node * C + c8 + 4) = o1;
    } else {
        __half* __restrict__ oh = (DST == 1) ? (__half*)g_H1 : (__half*)g_H2;
        __half2 h0 = __floats2half2_rn(di * ac[0], di * ac[1]);
        __half2 h1 = __floats2half2_rn(di * ac[2], di * ac[3]);
        __half2 h2 = __floats2half2_rn(di * ac[4], di * ac[5]);
        __half2 h3 = __floats2half2_rn(di * ac[6], di * ac[7]);
        uint4 o;
        o.x = *(uint32_t*)&h0; o.y = *(uint32_t*)&h1;
        o.z = *(uint32_t*)&h2; o.w = *(uint32_t*)&h3;
        *(uint4*)(oh + (size_t)node * C + c8) = o;
    }
}

// ---------------- launch: kernel launches ONLY -------------------------------
extern "C" void kernel_launch(void* const* d_in, const int* in_sizes, int n_in,
                              void* d_out, int out_size) {
    const float* x   = (const float*)d_in[0];
    // d_in[1] = edge_attr (unused by forward)
    const void*  ei  = d_in[2];
    const float* W1  = (const float*)d_in[3];
    const float* b1  = (const float*)d_in[4];
    const float* W2  = (const float*)d_in[5];
    const float* b2  = (const float*)d_in[6];
    const float* W3  = (const float*)d_in[7];
    const float* b3  = (const float*)d_in[8];
    float*       out = (float*)d_out;

    const int n = NN;
    const int e = in_sizes[2] / 2;             // 800000
    const int nblk = (n + 1023) / 1024;        // 49
    const int ntile = (n + 127) / 128;         // 391

    // ---- graph preprocessing + fp16 weight transposes
    k_zero_deg<<<(n + 255) / 256, 256>>>((const int*)ei, n);
    k_prep_edges<<<(e + 255) / 256, 256>>>(ei, e);
    k_scan<<<nblk, 1024>>>(n);
    k_fill_csr<<<(e + 255) / 256, 256>>>(ei, e);
    k_x2h<<<(NN * (C_IN / 8) + 255) / 256, 256>>>(x);
    k_w2h<0><<<dim3(256 / 32, 128 / 32), dim3(32, 8)>>>(W1, 128, 256);
    k_w2h<1><<<dim3(256 / 32, 256 / 32), dim3(32, 8)>>>(W2, 256, 256);
    k_w2h<2><<<dim3(64 / 32, 256 / 32), dim3(32, 8)>>>(W3, 256, 64);

    // ---- layer 1: agg H1 (128ch) -> H2; GEMM+bias+sig+dinv -> H1
    k_aggh<C_IN, 1, 2, false><<<NN / 8, 128>>>(nullptr, nullptr);
    k_gemm_f16<128, 0, 2, 1, true, true, true>
        <<<dim3(2, ntile), 256>>>(b1, n, 128, 256);
    // ---- layer 2: agg H1 (256ch) -> H2; GEMM+bias+sig -> H1
    k_aggh<C_HID, 1, 2, false><<<NN / 4, 128>>>(nullptr, nullptr);
    k_gemm_f16<128, 1, 2, 1, true, true, false>
        <<<dim3(2, ntile), 256>>>(b2, n, 256, 256);
    // ---- layer 3: GEMM H1 @ W3 +dinv -> H2 (64ch); agg + bias -> out
    k_gemm_f16<64, 2, 1, 2, false, false, true>
        <<<dim3(1, ntile), 256>>>(nullptr, n, 256, 64);
    k_aggh<C_OUT, 2, 0, true><<<NN / 16, 128>>>(b3, out);
}

// round 15
// speedup vs baseline: 1.5389x; 1.0651x over previous
#include <cuda_runtime.h>
#include <cuda_bf16.h>
#include <cuda_fp16.h>
#include <math.h>
#include <stdint.h>

// Problem constants (fixed by the dataset)
#define NN    50000     // nodes
#define EE    800000    // edges
#define C_IN  128
#define C_HID 256
#define C_OUT 64

// ---------------- scratch (device globals; no allocation, no host API) -----
__device__ int    g_is64;           // 1 if edge_index delivered as int64
__device__ int    g_deg[NN];
__device__ float  g_dinv[NN];
__device__ int    g_off[NN + 1];
__device__ int    g_cursor[NN];
__device__ int    g_csr[EE];
__device__ unsigned long long g_pkt[64];  // lookback packets: value<<2 | flag
__device__ __half g_H1[(size_t)NN * C_HID];   // fp16 feature ping
__device__ __half g_H2[(size_t)NN * C_HID];   // fp16 feature pong
__device__ __half g_W1h[256 * 128];   // W1^T fp16 [M][K]
__device__ __half g_W2h[256 * 256];   // W2^T
__device__ __half g_W3h[64 * 256];    // W3^T

// ---------------- prep ------------------------------------------------------
__global__ void k_zero_deg(const int* __restrict__ ei32, int n) {
    int i = blockIdx.x * blockDim.x + threadIdx.x;
    if (i < n) g_deg[i] = 0;
    if (i < 64) g_pkt[i] = 0ULL;
    if (blockIdx.x == 0 && threadIdx.x == 0) {
        int all_zero = 1;
        #pragma unroll
        for (int k = 0; k < 64; k++)
            if (ei32[2 * k + 1] != 0) all_zero = 0;
        g_is64 = all_zero;
    }
}

__global__ void k_prep_edges(const void* __restrict__ ei, int e) {
    int idx = blockIdx.x * blockDim.x + threadIdx.x;
    if (idx >= e) return;
    int c;
    if (g_is64) c = (int)((const long long*)ei)[(size_t)e + idx];
    else        c = ((const int*)ei)[(size_t)e + idx];
    atomicAdd(&g_deg[c], 1);
}

// single-pass decoupled-lookback scan (warp-parallel lookback):
// g_deg -> g_off/g_cursor, dinv fused. 49 blocks, all resident -> no deadlock.
__global__ void k_scan(int n) {
    __shared__ int wsum[32];
    __shared__ int s_excl;
    const int b = blockIdx.x;
    const int i = b * 1024 + threadIdx.x;
    const int v = (i < n) ? g_deg[i] : 0;
    const int lane = threadIdx.x & 31, w = threadIdx.x >> 5;

    int s = v;
    #pragma unroll
    for (int d = 1; d < 32; d <<= 1) {
        int t = __shfl_up_sync(~0u, s, d);
        if (lane >= d) s += t;
    }
    if (lane == 31) wsum[w] = s;
    __syncthreads();
    if (w == 0) {
        int ws = wsum[lane];
        #pragma unroll
        for (int d = 1; d < 32; d <<= 1) {
            int t = __shfl_up_sync(~0u, ws, d);
            if (lane >= d) ws += t;
        }
        wsum[lane] = ws;
    }
    __syncthreads();
    const int excl = s - v + (w > 0 ? wsum[w - 1] : 0);
    const int btotal = wsum[31];

    if (w == 0) {                         // warp-parallel lookback
        int ex = 0;
        if (b == 0) {
            if (lane == 0)
                atomicExch(&g_pkt[0], ((unsigned long long)btotal << 2) | 2ULL);
        } else {
            if (lane == 0)
                atomicExch(&g_pkt[b], ((unsigned long long)btotal << 2) | 1ULL);
            int base = b - 1;
            while (true) {
                int j = base - lane;
                unsigned long long p;
                if (j >= 0) {
                    do { p = atomicAdd(&g_pkt[j], 0ULL); } while ((p & 3ULL) == 0ULL);
                } else {
                    p = 2ULL;             // virtual prefix 0 below block 0
                }
                bool isPre = (p & 3ULL) == 2ULL;
                unsigned mask = __ballot_sync(~0u, isPre);
                int L = mask ? (__ffs(mask) - 1) : 31;   // nearest prefix lane
                int contrib = (lane <= L) ? (int)(p >> 2) : 0;
                #pragma unroll
                for (int d = 16; d; d >>= 1)
                    contrib += __shfl_down_sync(~0u, contrib, d);
                contrib = __shfl_sync(~0u, contrib, 0);
                ex += contrib;
                if (mask) break;
                base -= 32;
            }
            if (lane == 0)
                atomicExch(&g_pkt[b],
                           ((unsigned long long)(ex + btotal) << 2) | 2ULL);
        }
        if (lane == 0) s_excl = ex;
    }
    __syncthreads();

    const int off = s_excl + excl;
    if (i < n) {
        g_off[i] = off;
        g_cursor[i] = off;
        g_dinv[i] = rsqrtf((float)(v + 1));
    }
    if (i == n - 1) g_off[n] = off + v;
}

__global__ void k_fill_csr(const void* __restrict__ ei, int e) {
    int idx = blockIdx.x * blockDim.x + threadIdx.x;
    if (idx >= e) return;
    int r, c;
    if (g_is64) {
        const long long* p = (const long long*)ei;
        r = (int)p[idx];
        c = (int)p[(size_t)e + idx];
    } else {
        const int* p = (const int*)ei;
        r = p[idx];
        c = p[(size_t)e + idx];
    }
    int pos = atomicAdd(&g_cursor[c], 1);
    g_csr[pos] = r;
}

// fused conversions: x -> dinv-prescaled fp16 H1, W1/W2/W3 -> transposed fp16.
// grid partition: [0,3125) x2h; [3125,3157) W1; [3157,3221) W2; [3221,3237) W3
__global__ void k_convert(const float* __restrict__ x,
                          const float* __restrict__ W1,
                          const float* __restrict__ W2,
                          const float* __restrict__ W3) {
    int bx = blockIdx.x;
    if (bx < 3125) {                          // ---- x2h: 8 floats/thread
        int i = bx * 256 + threadIdx.x;
        int node = i >> 4;                    // C_IN/8 = 16 chunks per node
        float d = g_dinv[node];
        const float4* p = (const float4*)x + (size_t)i * 2;
        float4 a = __ldg(p), b = __ldg(p + 1);
        __half2 h0 = __floats2half2_rn(d * a.x, d * a.y);
        __half2 h1 = __floats2half2_rn(d * a.z, d * a.w);
        __half2 h2 = __floats2half2_rn(d * b.x, d * b.y);
        __half2 h3 = __floats2half2_rn(d * b.z, d * b.w);
        uint4 o;
        o.x = *(uint32_t*)&h0; o.y = *(uint32_t*)&h1;
        o.z = *(uint32_t*)&h2; o.w = *(uint32_t*)&h3;
        ((uint4*)g_H1)[i] = o;
        return;
    }
    // ---- weight transpose tiles (32x32)
    __shared__ float t[32][33];
    const float* W; __half* dst; int K, M, gx, idx;
    bx -= 3125;
    if (bx < 32)      { W = W1; dst = g_W1h; K = 128; M = 256; gx = 8; idx = bx; }
    else if (bx < 96) { W = W2; dst = g_W2h; K = 256; M = 256; gx = 8; idx = bx - 32; }
    else              { W = W3; dst = g_W3h; K = 256; M = 64;  gx = 2; idx = bx - 96; }
    int m0 = (idx % gx) * 32, k0 = (idx / gx) * 32;
    int tx = threadIdx.x & 31, ty = threadIdx.x >> 5;
    #pragma unroll
    for (int i = ty; i < 32; i += 8)
        t[tx][i] = W[(size_t)(k0 + i) * M + m0 + tx];
    __syncthreads();
    #pragma unroll
    for (int i = ty; i < 32; i += 8)
        dst[(size_t)(m0 + i) * K + k0 + tx] = __float2half(t[i][tx]);
}

// ---------------- fp16 HMMA helper (m16n8k16, fp32 accum) ---------------------
__device__ __forceinline__ void mma_f16(float c[4], const uint32_t a[4],
                                        const uint32_t b[2]) {
    asm volatile(
        "mma.sync.aligned.m16n8k16.row.col.f32.f16.f16.f32 "
        "{%0,%1,%2,%3}, {%4,%5,%6,%7}, {%8,%9}, {%0,%1,%2,%3};"
        : "+f"(c[0]), "+f"(c[1]), "+f"(c[2]), "+f"(c[3])
        : "r"(a[0]), "r"(a[1]), "r"(a[2]), "r"(a[3]), "r"(b[0]), "r"(b[1]));
}

// ---------------- fp16 GEMM: Out[N,M] = A[N,K] @ W[K,M] ----------------------
// A fp16 [N][K] (H1/H2), Wt fp16 [M][K] pre-transposed. BM=128, BK=32,
// double-buffered. 256 threads (8 warps 4x2), warp tile 32 x (BN/2).
// smem rows stride 20 half2: gi*20+ci is a bank permutation.
template <int BN, int WSEL, int SRC, int DST, bool SIG, bool BIAS, bool DSC>
__global__ __launch_bounds__(256)
void k_gemm_f16(const float* __restrict__ bias, int N, int K, int M) {
    const __half* __restrict__ A = (SRC == 1) ? (const __half*)g_H1
                                              : (const __half*)g_H2;
    __half* __restrict__ Out = (DST == 1) ? (__half*)g_H1 : (__half*)g_H2;
    const __half* __restrict__ Wt =
        (WSEL == 0) ? g_W1h : ((WSEL == 1) ? g_W2h : g_W3h);

    constexpr int WN   = BN / 2;
    constexpr int NT   = WN / 8;
    constexpr int NBLD = (BN == 128) ? 2 : 1;

    __shared__ __align__(16) uint32_t As[2][128 * 20];
    __shared__ __align__(16) uint32_t Bs[2][BN * 20];

    const int tid  = threadIdx.x;
    const int lane = tid & 31;
    const int warp = tid >> 5;
    const int wm   = warp >> 1;
    const int wn   = warp & 1;
    const int gi   = lane >> 2;
    const int ci   = lane & 3;
    const int row0 = blockIdx.y * 128;
    const int col0 = blockIdx.x * BN;

    float c[2][NT][4];
    #pragma unroll
    for (int mt = 0; mt < 2; mt++)
        #pragma unroll
        for (int nt = 0; nt < NT; nt++)
            #pragma unroll
            for (int j = 0; j < 4; j++) c[mt][nt][j] = 0.f;

    uint4 aR[2], bR[NBLD];
    const int KB = K / 32;

    auto load_regs = [&](int kb) {
        #pragma unroll
        for (int i = 0; i < 2; i++) {
            int idx = tid + i * 256;
            int r = idx >> 2, s = idx & 3;
            aR[i] = make_uint4(0u, 0u, 0u, 0u);
            if (row0 + r < N)
                aR[i] = *(const uint4*)(A + (size_t)(row0 + r) * K + kb * 32 + s * 8);
        }
        #pragma unroll
        for (int i = 0; i < NBLD; i++) {
            int idx = tid + i * 256;
            int r = idx >> 2, s = idx & 3;
            bR[i] = *(const uint4*)(Wt + (size_t)(col0 + r) * K + kb * 32 + s * 8);
        }
    };
    auto store_regs = [&](int st) {
        #pragma unroll
        for (int i = 0; i < 2; i++) {
            int idx = tid + i * 256;
            int r = idx >> 2, s = idx & 3;
            *(uint4*)&As[st][r * 20 + s * 4] = aR[i];
        }
        #pragma unroll
        for (int i = 0; i < NBLD; i++) {
            int idx = tid + i * 256;
            int r = idx >> 2, s = idx & 3;
            *(uint4*)&Bs[st][r * 20 + s * 4] = bR[i];
        }
    };

    load_regs(0);
    store_regs(0);
    __syncthreads();

    for (int kb = 0; kb < KB; kb++) {
        if (kb + 1 < KB) load_regs(kb + 1);
        const int st = kb & 1;

        #pragma unroll
        for (int kk = 0; kk < 2; kk++) {
            const int kbase = kk * 8 + ci;
            uint32_t a[2][4];
            #pragma unroll
            for (int mt = 0; mt < 2; mt++) {
                int mr = wm * 32 + mt * 16 + gi;
                a[mt][0] = As[st][mr * 20       + kbase];
                a[mt][1] = As[st][(mr + 8) * 20 + kbase];
                a[mt][2] = As[st][mr * 20       + kbase + 4];
                a[mt][3] = As[st][(mr + 8) * 20 + kbase + 4];
            }
            uint32_t b[NT][2];
            #pragma unroll
            for (int nt = 0; nt < NT; nt++) {
                int nc = wn * WN + nt * 8 + gi;
                b[nt][0] = Bs[st][nc * 20 + kbase];
                b[nt][1] = Bs[st][nc * 20 + kbase + 4];
            }
            #pragma unroll
            for (int mt = 0; mt < 2; mt++)
                #pragma unroll
                for (int nt = 0; nt < NT; nt++)
                    mma_f16(c[mt][nt], a[mt], b[nt]);
        }

        if (kb + 1 < KB) {
            store_regs((kb + 1) & 1);
            __syncthreads();
        }
    }

    // ---- epilogue: (+bias), (sigmoid), (dinv), store half2 pairs
    #pragma unroll
    for (int mt = 0; mt < 2; mt++) {
        int r = row0 + wm * 32 + mt * 16 + gi;
        float d0s = 1.f, d1s = 1.f;
        if (DSC) {
            if (r < N)     d0s = g_dinv[r];
            if (r + 8 < N) d1s = g_dinv[r + 8];
        }
        #pragma unroll
        for (int nt = 0; nt < NT; nt++) {
            int gcol = col0 + wn * WN + nt * 8 + ci * 2;
            float b0 = 0.f, b1 = 0.f;
            if (BIAS) { b0 = __ldg(bias + gcol); b1 = __ldg(bias + gcol + 1); }
            float v0 = c[mt][nt][0] + b0, v1 = c[mt][nt][1] + b1;
            float v2 = c[mt][nt][2] + b0, v3 = c[mt][nt][3] + b1;
            if (SIG) {
                v0 = 1.f / (1.f + __expf(-v0));
                v1 = 1.f / (1.f + __expf(-v1));
                v2 = 1.f / (1.f + __expf(-v2));
                v3 = 1.f / (1.f + __expf(-v3));
            }
            if (DSC) { v0 *= d0s; v1 *= d0s; v2 *= d1s; v3 *= d1s; }
            if (r < N)
                *(__half2*)(Out + (size_t)r * M + gcol) = __floats2half2_rn(v0, v1);
            if (r + 8 < N)
                *(__half2*)(Out + (size_t)(r + 8) * M + gcol) = __floats2half2_rn(v2, v3);
        }
    }
}

// ---------------- fp16 aggregation (8 halves/thread, 8-edge ILP) -------------
// rows prescaled by dinv: out[i] = dinv_i*(Σ_r in[r] + in[i]) (+bias)
// SRC: 1/2 = H1/H2.  DST: 0 = external fp32 out, 1/2 = H1/H2 fp16.
__device__ __forceinline__ void acc8(float ac[8], uint4 v) {
    float2 f0 = __half22float2(*reinterpret_cast<__half2*>(&v.x));
    float2 f1 = __half22float2(*reinterpret_cast<__half2*>(&v.y));
    float2 f2 = __half22float2(*reinterpret_cast<__half2*>(&v.z));
    float2 f3 = __half22float2(*reinterpret_cast<__half2*>(&v.w));
    ac[0] += f0.x; ac[1] += f0.y; ac[2] += f1.x; ac[3] += f1.y;
    ac[4] += f2.x; ac[5] += f2.y; ac[6] += f3.x; ac[7] += f3.y;
}

template <int C, int SRC, int DST, bool BIAS>
__global__ __launch_bounds__(128)
void k_aggh(const float* __restrict__ bias, float* __restrict__ out_ext) {
    constexpr int T   = C / 8;
    constexpr int NPB = 128 / T;
    const __half* __restrict__ in = (SRC == 1) ? (const __half*)g_H1
                                               : (const __half*)g_H2;

    const int node = blockIdx.x * NPB + threadIdx.x / T;
    if (node >= NN) return;
    const int c8 = (threadIdx.x % T) * 8;
    const float di = g_dinv[node];

    float ac[8] = {0.f, 0.f, 0.f, 0.f, 0.f, 0.f, 0.f, 0.f};
    acc8(ac, __ldg((const uint4*)(in + (size_t)node * C + c8)));   // self term

    int p = g_off[node];
    const int e = g_off[node + 1];
    for (; p + 7 < e; p += 8) {                      // 8-edge ILP
        int r0 = g_csr[p],     r1 = g_csr[p + 1];
        int r2 = g_csr[p + 2], r3 = g_csr[p + 3];
        int r4 = g_csr[p + 4], r5 = g_csr[p + 5];
        int r6 = g_csr[p + 6], r7 = g_csr[p + 7];
        uint4 v0 = __ldg((const uint4*)(in + (size_t)r0 * C + c8));
        uint4 v1 = __ldg((const uint4*)(in + (size_t)r1 * C + c8));
        uint4 v2 = __ldg((const uint4*)(in + (size_t)r2 * C + c8));
        uint4 v3 = __ldg((const uint4*)(in + (size_t)r3 * C + c8));
        uint4 v4 = __ldg((const uint4*)(in + (size_t)r4 * C + c8));
        uint4 v5 = __ldg((const uint4*)(in + (size_t)r5 * C + c8));
        uint4 v6 = __ldg((const uint4*)(in + (size_t)r6 * C + c8));
        uint4 v7 = __ldg((const uint4*)(in + (size_t)r7 * C + c8));
        acc8(ac, v0); acc8(ac, v1); acc8(ac, v2); acc8(ac, v3);
        acc8(ac, v4); acc8(ac, v5); acc8(ac, v6); acc8(ac, v7);
    }
    for (; p + 3 < e; p += 4) {
        int r0 = g_csr[p],     r1 = g_csr[p + 1];
        int r2 = g_csr[p + 2], r3 = g_csr[p + 3];
        uint4 v0 = __ldg((const uint4*)(in + (size_t)r0 * C + c8));
        uint4 v1 = __ldg((const uint4*)(in + (size_t)r1 * C + c8));
        uint4 v2 = __ldg((const uint4*)(in + (size_t)r2 * C + c8));
        uint4 v3 = __ldg((const uint4*)(in + (size_t)r3 * C + c8));
        acc8(ac, v0); acc8(ac, v1); acc8(ac, v2); acc8(ac, v3);
    }
    for (; p < e; p++)
        acc8(ac, __ldg((const uint4*)(in + (size_t)g_csr[p] * C + c8)));

    if (DST == 0) {
        float4 o0 = make_float4(di * ac[0], di * ac[1], di * ac[2], di * ac[3]);
        float4 o1 = make_float4(di * ac[4], di * ac[5], di * ac[6], di * ac[7]);
        if (BIAS) {
            float4 b0 = __ldg((const float4*)(bias + c8));
            float4 b1 = __ldg((const float4*)(bias + c8 + 4));
            o0.x += b0.x; o0.y += b0.y; o0.z += b0.z; o0.w += b0.w;
            o1.x += b1.x; o1.y += b1.y; o1.z += b1.z; o1.w += b1.w;
        }
        *(float4*)(out_ext + (size_t)node * C + c8)     = o0;
        *(float4*)(out_ext + (size_t)node * C + c8 + 4) = o1;
    } else {
        __half* __restrict__ oh = (DST == 1) ? (__half*)g_H1 : (__half*)g_H2;
        __half2 h0 = __floats2half2_rn(di * ac[0], di * ac[1]);
        __half2 h1 = __floats2half2_rn(di * ac[2], di * ac[3]);
        __half2 h2 = __floats2half2_rn(di * ac[4], di * ac[5]);
        __half2 h3 = __floats2half2_rn(di * ac[6], di * ac[7]);
        uint4 o;
        o.x = *(uint32_t*)&h0; o.y = *(uint32_t*)&h1;
        o.z = *(uint32_t*)&h2; o.w = *(uint32_t*)&h3;
        *(uint4*)(oh + (size_t)node * C + c8) = o;
    }
}

// ---------------- launch: kernel launches ONLY -------------------------------
extern "C" void kernel_launch(void* const* d_in, const int* in_sizes, int n_in,
                              void* d_out, int out_size) {
    const float* x   = (const float*)d_in[0];
    // d_in[1] = edge_attr (unused by forward)
    const void*  ei  = d_in[2];
    const float* W1  = (const float*)d_in[3];
    const float* b1  = (const float*)d_in[4];
    const float* W2  = (const float*)d_in[5];
    const float* b2  = (const float*)d_in[6];
    const float* W3  = (const float*)d_in[7];
    const float* b3  = (const float*)d_in[8];
    float*       out = (float*)d_out;

    const int n = NN;
    const int e = in_sizes[2] / 2;             // 800000
    const int nblk = (n + 1023) / 1024;        // 49
    const int ntile = (n + 127) / 128;         // 391

    // ---- graph preprocessing + fused conversions
    k_zero_deg<<<(n + 255) / 256, 256>>>((const int*)ei, n);
    k_prep_edges<<<(e + 255) / 256, 256>>>(ei, e);
    k_scan<<<nblk, 1024>>>(n);
    k_fill_csr<<<(e + 255) / 256, 256>>>(ei, e);
    k_convert<<<3237, 256>>>(x, W1, W2, W3);   // x2h + 3 weight transposes

    // ---- layer 1: agg H1 (128ch) -> H2; GEMM+bias+sig+dinv -> H1
    k_aggh<C_IN, 1, 2, false><<<NN / 8, 128>>>(nullptr, nullptr);
    k_gemm_f16<128, 0, 2, 1, true, true, true>
        <<<dim3(2, ntile), 256>>>(b1, n, 128, 256);
    // ---- layer 2: agg H1 (256ch) -> H2; GEMM+bias+sig -> H1
    k_aggh<C_HID, 1, 2, false><<<NN / 4, 128>>>(nullptr, nullptr);
    k_gemm_f16<128, 1, 2, 1, true, true, false>
        <<<dim3(2, ntile), 256>>>(b2, n, 256, 256);
    // ---- layer 3: GEMM H1 @ W3 +dinv -> H2 (64ch); agg + bias -> out
    k_gemm_f16<64, 2, 1, 2, false, false, true>
        <<<dim3(1, ntile), 256>>>(nullptr, n, 256, 64);
    k_aggh<C_OUT, 2, 0, true><<<NN / 16, 128>>>(b3, out);
}

// round 16
// speedup vs baseline: 1.5425x; 1.0024x over previous
#include <cuda_runtime.h>
#include <cuda_bf16.h>
#include <cuda_fp16.h>
#include <math.h>
#include <stdint.h>

// Problem constants (fixed by the dataset)
#define NN    50000     // nodes
#define EE    800000    // edges
#define C_IN  128
#define C_HID 256
#define C_OUT 64

// ---------------- scratch (device globals; no allocation, no host API) -----
__device__ int    g_is64;           // 1 if edge_index delivered as int64
__device__ int    g_deg[NN];
__device__ float  g_dinv[NN];
__device__ int    g_off[NN + 1];
__device__ int    g_cursor[NN];
__device__ int    g_csr[EE];
__device__ unsigned long long g_pkt[64];  // lookback packets: value<<2 | flag
__device__ __half g_H1[(size_t)NN * C_HID];   // fp16 feature ping
__device__ __half g_H2[(size_t)NN * C_HID];   // fp16 feature pong
__device__ __half g_W1h[256 * 128];   // W1^T fp16 [M][K]
__device__ __half g_W2h[256 * 256];   // W2^T
__device__ __half g_W3h[64 * 256];    // W3^T

// ---------------- prep ------------------------------------------------------
__global__ void k_zero_deg(const int* __restrict__ ei32, int n) {
    int i = blockIdx.x * blockDim.x + threadIdx.x;
    if (i < n) g_deg[i] = 0;
    if (i < 64) g_pkt[i] = 0ULL;
    if (blockIdx.x == 0 && threadIdx.x == 0) {
        int all_zero = 1;
        #pragma unroll
        for (int k = 0; k < 64; k++)
            if (ei32[2 * k + 1] != 0) all_zero = 0;
        g_is64 = all_zero;
    }
}

// degree count, 4 edges per thread (vectorized col reads)
__global__ void k_prep_edges(const void* __restrict__ ei, int e) {
    int i4 = (blockIdx.x * blockDim.x + threadIdx.x) * 4;
    if (i4 >= e) return;
    int c[4]; int m = e - i4; if (m > 4) m = 4;
    if (g_is64) {
        const long long* p = (const long long*)ei + e;
        if (m == 4) {
            longlong2 a = __ldg((const longlong2*)(p + i4));
            longlong2 b = __ldg((const longlong2*)(p + i4 + 2));
            c[0] = (int)a.x; c[1] = (int)a.y; c[2] = (int)b.x; c[3] = (int)b.y;
        } else {
            for (int j = 0; j < m; j++) c[j] = (int)p[i4 + j];
        }
    } else {
        const int* p = (const int*)ei + e;
        if (m == 4) {
            int4 a = __ldg((const int4*)(p + i4));
            c[0] = a.x; c[1] = a.y; c[2] = a.z; c[3] = a.w;
        } else {
            for (int j = 0; j < m; j++) c[j] = p[i4 + j];
        }
    }
    for (int j = 0; j < m; j++) atomicAdd(&g_deg[c[j]], 1);
}

// single-pass decoupled-lookback scan (warp-parallel lookback):
// g_deg -> g_off/g_cursor, dinv fused. 49 blocks, all resident -> no deadlock.
__global__ void k_scan(int n) {
    __shared__ int wsum[32];
    __shared__ int s_excl;
    const int b = blockIdx.x;
    const int i = b * 1024 + threadIdx.x;
    const int v = (i < n) ? g_deg[i] : 0;
    const int lane = threadIdx.x & 31, w = threadIdx.x >> 5;

    int s = v;
    #pragma unroll
    for (int d = 1; d < 32; d <<= 1) {
        int t = __shfl_up_sync(~0u, s, d);
        if (lane >= d) s += t;
    }
    if (lane == 31) wsum[w] = s;
    __syncthreads();
    if (w == 0) {
        int ws = wsum[lane];
        #pragma unroll
        for (int d = 1; d < 32; d <<= 1) {
            int t = __shfl_up_sync(~0u, ws, d);
            if (lane >= d) ws += t;
        }
        wsum[lane] = ws;
    }
    __syncthreads();
    const int excl = s - v + (w > 0 ? wsum[w - 1] : 0);
    const int btotal = wsum[31];

    if (w == 0) {                         // warp-parallel lookback
        int ex = 0;
        if (b == 0) {
            if (lane == 0)
                atomicExch(&g_pkt[0], ((unsigned long long)btotal << 2) | 2ULL);
        } else {
            if (lane == 0)
                atomicExch(&g_pkt[b], ((unsigned long long)btotal << 2) | 1ULL);
            int base = b - 1;
            while (true) {
                int j = base - lane;
                unsigned long long p;
                if (j >= 0) {
                    do { p = atomicAdd(&g_pkt[j], 0ULL); } while ((p & 3ULL) == 0ULL);
                } else {
                    p = 2ULL;             // virtual prefix 0 below block 0
                }
                bool isPre = (p & 3ULL) == 2ULL;
                unsigned mask = __ballot_sync(~0u, isPre);
                int L = mask ? (__ffs(mask) - 1) : 31;
                int contrib = (lane <= L) ? (int)(p >> 2) : 0;
                #pragma unroll
                for (int d = 16; d; d >>= 1)
                    contrib += __shfl_down_sync(~0u, contrib, d);
                contrib = __shfl_sync(~0u, contrib, 0);
                ex += contrib;
                if (mask) break;
                base -= 32;
            }
            if (lane == 0)
                atomicExch(&g_pkt[b],
                           ((unsigned long long)(ex + btotal) << 2) | 2ULL);
        }
        if (lane == 0) s_excl = ex;
    }
    __syncthreads();

    const int off = s_excl + excl;
    if (i < n) {
        g_off[i] = off;
        g_cursor[i] = off;
        g_dinv[i] = rsqrtf((float)(v + 1));
    }
    if (i == n - 1) g_off[n] = off + v;
}

// fill CSR, 4 edges per thread (independent atomic chains for MLP)
__global__ void k_fill_csr(const void* __restrict__ ei, int e) {
    int i4 = (blockIdx.x * blockDim.x + threadIdx.x) * 4;
    if (i4 >= e) return;
    int r[4], c[4]; int m = e - i4; if (m > 4) m = 4;
    if (g_is64) {
        const long long* pr = (const long long*)ei;
        const long long* pc = pr + e;
        if (m == 4) {
            longlong2 a = __ldg((const longlong2*)(pr + i4));
            longlong2 b = __ldg((const longlong2*)(pr + i4 + 2));
            longlong2 x = __ldg((const longlong2*)(pc + i4));
            longlong2 y = __ldg((const longlong2*)(pc + i4 + 2));
            r[0] = (int)a.x; r[1] = (int)a.y; r[2] = (int)b.x; r[3] = (int)b.y;
            c[0] = (int)x.x; c[1] = (int)x.y; c[2] = (int)y.x; c[3] = (int)y.y;
        } else {
            for (int j = 0; j < m; j++) { r[j] = (int)pr[i4 + j]; c[j] = (int)pc[i4 + j]; }
        }
    } else {
        const int* pr = (const int*)ei;
        const int* pc = pr + e;
        if (m == 4) {
            int4 a = __ldg((const int4*)(pr + i4));
            int4 x = __ldg((const int4*)(pc + i4));
            r[0] = a.x; r[1] = a.y; r[2] = a.z; r[3] = a.w;
            c[0] = x.x; c[1] = x.y; c[2] = x.z; c[3] = x.w;
        } else {
            for (int j = 0; j < m; j++) { r[j] = pr[i4 + j]; c[j] = pc[i4 + j]; }
        }
    }
    int pos[4];
    for (int j = 0; j < m; j++) pos[j] = atomicAdd(&g_cursor[c[j]], 1);
    for (int j = 0; j < m; j++) g_csr[pos[j]] = r[j];
}

// fused conversions: x -> dinv-prescaled fp16 H1, W1/W2/W3 -> transposed fp16.
__global__ void k_convert(const float* __restrict__ x,
                          const float* __restrict__ W1,
                          const float* __restrict__ W2,
                          const float* __restrict__ W3) {
    int bx = blockIdx.x;
    if (bx < 3125) {                          // ---- x2h: 8 floats/thread
        int i = bx * 256 + threadIdx.x;
        int node = i >> 4;
        float d = g_dinv[node];
        const float4* p = (const float4*)x + (size_t)i * 2;
        float4 a = __ldg(p), b = __ldg(p + 1);
        __half2 h0 = __floats2half2_rn(d * a.x, d * a.y);
        __half2 h1 = __floats2half2_rn(d * a.z, d * a.w);
        __half2 h2 = __floats2half2_rn(d * b.x, d * b.y);
        __half2 h3 = __floats2half2_rn(d * b.z, d * b.w);
        uint4 o;
        o.x = *(uint32_t*)&h0; o.y = *(uint32_t*)&h1;
        o.z = *(uint32_t*)&h2; o.w = *(uint32_t*)&h3;
        ((uint4*)g_H1)[i] = o;
        return;
    }
    __shared__ float t[32][33];
    const float* W; __half* dst; int K, M, gx, idx;
    bx -= 3125;
    if (bx < 32)      { W = W1; dst = g_W1h; K = 128; M = 256; gx = 8; idx = bx; }
    else if (bx < 96) { W = W2; dst = g_W2h; K = 256; M = 256; gx = 8; idx = bx - 32; }
    else              { W = W3; dst = g_W3h; K = 256; M = 64;  gx = 2; idx = bx - 96; }
    int m0 = (idx % gx) * 32, k0 = (idx / gx) * 32;
    int tx = threadIdx.x & 31, ty = threadIdx.x >> 5;
    #pragma unroll
    for (int i = ty; i < 32; i += 8)
        t[tx][i] = W[(size_t)(k0 + i) * M + m0 + tx];
    __syncthreads();
    #pragma unroll
    for (int i = ty; i < 32; i += 8)
        dst[(size_t)(m0 + i) * K + k0 + tx] = __float2half(t[i][tx]);
}

// ---------------- fp16 HMMA + ldmatrix helpers --------------------------------
__device__ __forceinline__ void mma_f16(float c[4], const uint32_t a[4],
                                        const uint32_t b[2]) {
    asm volatile(
        "mma.sync.aligned.m16n8k16.row.col.f32.f16.f16.f32 "
        "{%0,%1,%2,%3}, {%4,%5,%6,%7}, {%8,%9}, {%0,%1,%2,%3};"
        : "+f"(c[0]), "+f"(c[1]), "+f"(c[2]), "+f"(c[3])
        : "r"(a[0]), "r"(a[1]), "r"(a[2]), "r"(a[3]), "r"(b[0]), "r"(b[1]));
}

__device__ __forceinline__ void ldsm_x4(uint32_t r[4], uint32_t saddr) {
    asm volatile(
        "ldmatrix.sync.aligned.m8n8.x4.shared.b16 {%0,%1,%2,%3}, [%4];"
        : "=r"(r[0]), "=r"(r[1]), "=r"(r[2]), "=r"(r[3]) : "r"(saddr));
}

__device__ __forceinline__ uint32_t smem_u32(const void* p) {
    uint32_t a;
    asm("{ .reg .u64 t; cvta.to.shared.u64 t, %1; cvt.u32.u64 %0, t; }"
        : "=r"(a) : "l"(p));
    return a;
}

// ---------------- fp16 GEMM: Out[N,M] = A[N,K] @ W[K,M] ----------------------
// A fp16 [N][K] (H1/H2), Wt fp16 [M][K] pre-transposed. BM=128, BK=32,
// double-buffered, ldmatrix fragment loads. 256 threads (8 warps 4x2),
// warp tile 32 x (BN/2). smem row stride 80B (20 half2): ldmatrix 8-row groups
// hit word offsets {0,20,8,28,16,4,24,12} mod 32 -> conflict-free.
template <int BN, int WSEL, int SRC, int DST, bool SIG, bool BIAS, bool DSC>
__global__ __launch_bounds__(256)
void k_gemm_f16(const float* __restrict__ bias, int N, int K, int M) {
    const __half* __restrict__ A = (SRC == 1) ? (const __half*)g_H1
                                              : (const __half*)g_H2;
    __half* __restrict__ Out = (DST == 1) ? (__half*)g_H1 : (__half*)g_H2;
    const __half* __restrict__ Wt =
        (WSEL == 0) ? g_W1h : ((WSEL == 1) ? g_W2h : g_W3h);

    constexpr int WN   = BN / 2;
    constexpr int NT   = WN / 8;
    constexpr int NBLD = (BN == 128) ? 2 : 1;

    __shared__ __align__(16) uint32_t As[2][128 * 20];
    __shared__ __align__(16) uint32_t Bs[2][BN * 20];

    const int tid  = threadIdx.x;
    const int lane = tid & 31;
    const int warp = tid >> 5;
    const int wm   = warp >> 1;
    const int wn   = warp & 1;
    const int gi   = lane >> 2;
    const int ci   = lane & 3;
    const int row0 = blockIdx.y * 128;
    const int col0 = blockIdx.x * BN;

    float c[2][NT][4];
    #pragma unroll
    for (int mt = 0; mt < 2; mt++)
        #pragma unroll
        for (int nt = 0; nt < NT; nt++)
            #pragma unroll
            for (int j = 0; j < 4; j++) c[mt][nt][j] = 0.f;

    uint4 aR[2], bR[NBLD];
    const int KB = K / 32;

    auto load_regs = [&](int kb) {
        #pragma unroll
        for (int i = 0; i < 2; i++) {
            int idx = tid + i * 256;
            int r = idx >> 2, s = idx & 3;
            aR[i] = make_uint4(0u, 0u, 0u, 0u);
            if (row0 + r < N)
                aR[i] = *(const uint4*)(A + (size_t)(row0 + r) * K + kb * 32 + s * 8);
        }
        #pragma unroll
        for (int i = 0; i < NBLD; i++) {
            int idx = tid + i * 256;
            int r = idx >> 2, s = idx & 3;
            bR[i] = *(const uint4*)(Wt + (size_t)(col0 + r) * K + kb * 32 + s * 8);
        }
    };
    auto store_regs = [&](int st) {
        #pragma unroll
        for (int i = 0; i < 2; i++) {
            int idx = tid + i * 256;
            int r = idx >> 2, s = idx & 3;
            *(uint4*)&As[st][r * 20 + s * 4] = aR[i];
        }
        #pragma unroll
        for (int i = 0; i < NBLD; i++) {
            int idx = tid + i * 256;
            int r = idx >> 2, s = idx & 3;
            *(uint4*)&Bs[st][r * 20 + s * 4] = bR[i];
        }
    };

    // ---- ldmatrix per-lane base addresses (byte offsets within a stage) ----
    // A: matrices (rows0-7,k0)(rows8-15,k0)(rows0-7,k8)(rows8-15,k8) -> a0..a3
    const int lg = lane >> 3, lr = lane & 7;       // group 0..3, row-in-group
    const uint32_t aOff =
        (uint32_t)((wm * 32 + (lg & 1) * 8 + lr) * 80 + (lg >> 1) * 16);
    // B: matrices (nt0,k0)(nt0,k8)(nt1,k0)(nt1,k8) -> b[nt0][0..1], b[nt1][0..1]
    const uint32_t bOff =
        (uint32_t)((wn * WN + (lg >> 1) * 8 + lr) * 80 + (lg & 1) * 16);
    const uint32_t uAs = smem_u32(&As[0][0]);
    const uint32_t uBs = smem_u32(&Bs[0][0]);
    constexpr uint32_t ASTAGE = 128 * 20 * 4;
    constexpr uint32_t BSTAGE = BN * 20 * 4;

    load_regs(0);
    store_regs(0);
    __syncthreads();

    for (int kb = 0; kb < KB; kb++) {
        if (kb + 1 < KB) load_regs(kb + 1);
        const int st = kb & 1;
        const uint32_t aBase = uAs + st * ASTAGE + aOff;
        const uint32_t bBase = uBs + st * BSTAGE + bOff;

        #pragma unroll
        for (int kk = 0; kk < 2; kk++) {
            uint32_t a[2][4];
            #pragma unroll
            for (int mt = 0; mt < 2; mt++)
                ldsm_x4(a[mt], aBase + mt * (16 * 80) + kk * 32);
            uint32_t b[NT][2];
            #pragma unroll
            for (int j = 0; j < NT / 2; j++) {
                uint32_t br[4];
                ldsm_x4(br, bBase + j * (16 * 80) + kk * 32);
                b[2 * j][0] = br[0]; b[2 * j][1] = br[1];
                b[2 * j + 1][0] = br[2]; b[2 * j + 1][1] = br[3];
            }
            #pragma unroll
            for (int mt = 0; mt < 2; mt++)
                #pragma unroll
                for (int nt = 0; nt < NT; nt++)
                    mma_f16(c[mt][nt], a[mt], b[nt]);
        }

        if (kb + 1 < KB) {
            store_regs((kb + 1) & 1);
            __syncthreads();
        }
    }

    // ---- epilogue: (+bias), (sigmoid), (dinv), store half2 pairs
    #pragma unroll
    for (int mt = 0; mt < 2; mt++) {
        int r = row0 + wm * 32 + mt * 16 + gi;
        float d0s = 1.f, d1s = 1.f;
        if (DSC) {
            if (r < N)     d0s = g_dinv[r];
            if (r + 8 < N) d1s = g_dinv[r + 8];
        }
        #pragma unroll
        for (int nt = 0; nt < NT; nt++) {
            int gcol = col0 + wn * WN + nt * 8 + ci * 2;
            float b0 = 0.f, b1 = 0.f;
            if (BIAS) { b0 = __ldg(bias + gcol); b1 = __ldg(bias + gcol + 1); }
            float v0 = c[mt][nt][0] + b0, v1 = c[mt][nt][1] + b1;
            float v2 = c[mt][nt][2] + b0, v3 = c[mt][nt][3] + b1;
            if (SIG) {
                v0 = 1.f / (1.f + __expf(-v0));
                v1 = 1.f / (1.f + __expf(-v1));
                v2 = 1.f / (1.f + __expf(-v2));
                v3 = 1.f / (1.f + __expf(-v3));
            }
            if (DSC) { v0 *= d0s; v1 *= d0s; v2 *= d1s; v3 *= d1s; }
            if (r < N)
                *(__half2*)(Out + (size_t)r * M + gcol) = __floats2half2_rn(v0, v1);
            if (r + 8 < N)
                *(__half2*)(Out + (size_t)(r + 8) * M + gcol) = __floats2half2_rn(v2, v3);
        }
    }
}

// ---------------- fp16 aggregation (8 halves/thread, 8-edge ILP) -------------
__device__ __forceinline__ void acc8(float ac[8], uint4 v) {
    float2 f0 = __half22float2(*reinterpret_cast<__half2*>(&v.x));
    float2 f1 = __half22float2(*reinterpret_cast<__half2*>(&v.y));
    float2 f2 = __half22float2(*reinterpret_cast<__half2*>(&v.z));
    float2 f3 = __half22float2(*reinterpret_cast<__half2*>(&v.w));
    ac[0] += f0.x; ac[1] += f0.y; ac[2] += f1.x; ac[3] += f1.y;
    ac[4] += f2.x; ac[5] += f2.y; ac[6] += f3.x; ac[7] += f3.y;
}

template <int C, int SRC, int DST, bool BIAS>
__global__ __launch_bounds__(128)
void k_aggh(const float* __restrict__ bias, float* __restrict__ out_ext) {
    constexpr int T   = C / 8;
    constexpr int NPB = 128 / T;
    const __half* __restrict__ in = (SRC == 1) ? (const __half*)g_H1
                                               : (const __half*)g_H2;

    const int node = blockIdx.x * NPB + threadIdx.x / T;
    if (node >= NN) return;
    const int c8 = (threadIdx.x % T) * 8;
    const float di = g_dinv[node];

    float ac[8] = {0.f, 0.f, 0.f, 0.f, 0.f, 0.f, 0.f, 0.f};
    acc8(ac, __ldg((const uint4*)(in + (size_t)node * C + c8)));   // self term

    int p = g_off[node];
    const int e = g_off[node + 1];
    for (; p + 7 < e; p += 8) {
        int r0 = g_csr[p],     r1 = g_csr[p + 1];
        int r2 = g_csr[p + 2], r3 = g_csr[p + 3];
        int r4 = g_csr[p + 4], r5 = g_csr[p + 5];
        int r6 = g_csr[p + 6], r7 = g_csr[p + 7];
        uint4 v0 = __ldg((const uint4*)(in + (size_t)r0 * C + c8));
        uint4 v1 = __ldg((const uint4*)(in + (size_t)r1 * C + c8));
        uint4 v2 = __ldg((const uint4*)(in + (size_t)r2 * C + c8));
        uint4 v3 = __ldg((const uint4*)(in + (size_t)r3 * C + c8));
        uint4 v4 = __ldg((const uint4*)(in + (size_t)r4 * C + c8));
        uint4 v5 = __ldg((const uint4*)(in + (size_t)r5 * C + c8));
        uint4 v6 = __ldg((const uint4*)(in + (size_t)r6 * C + c8));
        uint4 v7 = __ldg((const uint4*)(in + (size_t)r7 * C + c8));
        acc8(ac, v0); acc8(ac, v1); acc8(ac, v2); acc8(ac, v3);
        acc8(ac, v4); acc8(ac, v5); acc8(ac, v6); acc8(ac, v7);
    }
    for (; p + 3 < e; p += 4) {
        int r0 = g_csr[p],     r1 = g_csr[p + 1];
        int r2 = g_csr[p + 2], r3 = g_csr[p + 3];
        uint4 v0 = __ldg((const uint4*)(in + (size_t)r0 * C + c8));
        uint4 v1 = __ldg((const uint4*)(in + (size_t)r1 * C + c8));
        uint4 v2 = __ldg((const uint4*)(in + (size_t)r2 * C + c8));
        uint4 v3 = __ldg((const uint4*)(in + (size_t)r3 * C + c8));
        acc8(ac, v0); acc8(ac, v1); acc8(ac, v2); acc8(ac, v3);
    }
    for (; p < e; p++)
        acc8(ac, __ldg((const uint4*)(in + (size_t)g_csr[p] * C + c8)));

    if (DST == 0) {
        float4 o0 = make_float4(di * ac[0], di * ac[1], di * ac[2], di * ac[3]);
        float4 o1 = make_float4(di * ac[4], di * ac[5], di * ac[6], di * ac[7]);
        if (BIAS) {
            float4 b0 = __ldg((const float4*)(bias + c8));
            float4 b1 = __ldg((const float4*)(bias + c8 + 4));
            o0.x += b0.x; o0.y += b0.y; o0.z += b0.z; o0.w += b0.w;
            o1.x += b1.x; o1.y += b1.y; o1.z += b1.z; o1.w += b1.w;
        }
        *(float4*)(out_ext + (size_t)node * C + c8)     = o0;
        *(float4*)(out_ext + (size_t)node * C + c8 + 4) = o1;
    } else {
        __half* __restrict__ oh = (DST == 1) ? (__half*)g_H1 : (__half*)g_H2;
        __half2 h0 = __floats2half2_rn(di * ac[0], di * ac[1]);
        __half2 h1 = __floats2half2_rn(di * ac[2], di * ac[3]);
        __half2 h2 = __floats2half2_rn(di * ac[4], di * ac[5]);
        __half2 h3 = __floats2half2_rn(di * ac[6], di * ac[7]);
        uint4 o;
        o.x = *(uint32_t*)&h0; o.y = *(uint32_t*)&h1;
        o.z = *(uint32_t*)&h2; o.w = *(uint32_t*)&h3;
        *(uint4*)(oh + (size_t)node * C + c8) = o;
    }
}

// ---------------- launch: kernel launches ONLY -------------------------------
extern "C" void kernel_launch(void* const* d_in, const int* in_sizes, int n_in,
                              void* d_out, int out_size) {
    const float* x   = (const float*)d_in[0];
    // d_in[1] = edge_attr (unused by forward)
    const void*  ei  = d_in[2];
    const float* W1  = (const float*)d_in[3];
    const float* b1  = (const float*)d_in[4];
    const float* W2  = (const float*)d_in[5];
    const float* b2  = (const float*)d_in[6];
    const float* W3  = (const float*)d_in[7];
    const float* b3  = (const float*)d_in[8];
    float*       out = (float*)d_out;

    const int n = NN;
    const int e = in_sizes[2] / 2;             // 800000
    const int nblk = (n + 1023) / 1024;        // 49
    const int ntile = (n + 127) / 128;         // 391
    const int e4 = (e + 3) / 4;

    // ---- graph preprocessing + fused conversions
    k_zero_deg<<<(n + 255) / 256, 256>>>((const int*)ei, n);
    k_prep_edges<<<(e4 + 255) / 256, 256>>>(ei, e);
    k_scan<<<nblk, 1024>>>(n);
    k_fill_csr<<<(e4 + 255) / 256, 256>>>(ei, e);
    k_convert<<<3237, 256>>>(x, W1, W2, W3);

    // ---- layer 1: agg H1 (128ch) -> H2; GEMM+bias+sig+dinv -> H1
    k_aggh<C_IN, 1, 2, false><<<NN / 8, 128>>>(nullptr, nullptr);
    k_gemm_f16<128, 0, 2, 1, true, true, true>
        <<<dim3(2, ntile), 256>>>(b1, n, 128, 256);
    // ---- layer 2: agg H1 (256ch) -> H2; GEMM+bias+sig -> H1
    k_aggh<C_HID, 1, 2, false><<<NN / 4, 128>>>(nullptr, nullptr);
    k_gemm_f16<128, 1, 2, 1, true, true, false>
        <<<dim3(2, ntile), 256>>>(b2, n, 256, 256);
    // ---- layer 3: GEMM H1 @ W3 +dinv -> H2 (64ch); agg + bias -> out
    k_gemm_f16<64, 2, 1, 2, false, false, true>
        <<<dim3(1, ntile), 256>>>(nullptr, n, 256, 64);
    k_aggh<C_OUT, 2, 0, true><<<NN / 16, 128>>>(b3, out);
}